// round 5
// baseline (speedup 1.0000x reference)
#include <cuda_runtime.h>
#include <cuda_bf16.h>
#include <cstdint>

#define D 128
#define MAXN 40000

// ------------------------- device scratch (no allocs) -----------------------
__device__ __align__(16) float g_AB[(size_t)MAXN * 256]; // [N][256]: A=nf@W1^T | B'=nf@W2^T+b_e
__device__ __align__(16) float g_agg[(size_t)MAXN * D];
__device__ __align__(16) float g_deg[MAXN];
__device__ __align__(16) __nv_bfloat16 g_We_hi[128 * 384];
__device__ __align__(16) __nv_bfloat16 g_We_lo[128 * 384];
__device__ __align__(16) __nv_bfloat16 g_Wn_hi[128 * 256];
__device__ __align__(16) __nv_bfloat16 g_Wn_lo[128 * 256];

// ------------------------- smem layout --------------------------------------
#define ROWB 272                 // 136 bf16/row; 68 words -> 4-bank shift/row, LDSM conflict-free
#define BUF_LO 34816             // lo plane offset inside one hi/lo buffer (128*272)
#define BUF_SZ 69632             // one hi+lo buffer
// k_edge / k_pre: A0 @0, A1 @BUF_SZ, B @2*BUF_SZ
// k_node:         A  @0, B0 @BUF_SZ, B1 @2*BUF_SZ
#define SMEM_BYTES (3 * BUF_SZ)  // 208896

__device__ __forceinline__ uint32_t smem_u32(const void* p) {
    uint32_t a;
    asm("{ .reg .u64 t; cvta.to.shared.u64 t, %1; cvt.u32.u64 %0, t; }" : "=r"(a) : "l"(p));
    return a;
}

#define LDM4(r, addr) \
    asm volatile("ldmatrix.sync.aligned.m8n8.x4.shared.b16 {%0,%1,%2,%3}, [%4];" \
        : "=r"((r)[0]), "=r"((r)[1]), "=r"((r)[2]), "=r"((r)[3]) : "r"(addr))

__device__ __forceinline__ void mma16816(float* c, const uint32_t* a, const uint32_t* b) {
    asm volatile("mma.sync.aligned.m16n8k16.row.col.f32.bf16.bf16.f32 "
        "{%0,%1,%2,%3}, {%4,%5,%6,%7}, {%8,%9}, {%0,%1,%2,%3};"
        : "+f"(c[0]), "+f"(c[1]), "+f"(c[2]), "+f"(c[3])
        : "r"(a[0]), "r"(a[1]), "r"(a[2]), "r"(a[3]), "r"(b[0]), "r"(b[1]));
}

__device__ __forceinline__ void split2(float x, float y, uint32_t& h, uint32_t& l) {
    __nv_bfloat162 hh = __floats2bfloat162_rn(x, y);
    __nv_bfloat162 ll = __floats2bfloat162_rn(x - __bfloat162float(hh.x),
                                              y - __bfloat162float(hh.y));
    h = *reinterpret_cast<uint32_t*>(&hh);
    l = *reinterpret_cast<uint32_t*>(&ll);
}

// A tile fill (512 thr): 128 rows x 128 k fp32 -> bf16 hi/lo
__device__ __forceinline__ void fill_A(char* abuf, const float* __restrict__ g,
                                       int row0, int nrows, const float* __restrict__ deg,
                                       int tid) {
    int row = tid >> 2, q = tid & 3;
    if (row < nrows) {
        float s = 1.f;
        if (deg) s = 1.f / fmaxf(deg[row0 + row], 1.f);
        const float* gr = g + (size_t)(row0 + row) * D + q * 32;
        char* ph = abuf + row * ROWB + q * 64;
        char* pl = ph + BUF_LO;
        #pragma unroll
        for (int j = 0; j < 4; ++j) {
            float4 f0 = *reinterpret_cast<const float4*>(gr + j * 8);
            float4 f1 = *reinterpret_cast<const float4*>(gr + j * 8 + 4);
            f0.x *= s; f0.y *= s; f0.z *= s; f0.w *= s;
            f1.x *= s; f1.y *= s; f1.z *= s; f1.w *= s;
            uint4 H, L;
            split2(f0.x, f0.y, H.x, L.x);
            split2(f0.z, f0.w, H.y, L.y);
            split2(f1.x, f1.y, H.z, L.z);
            split2(f1.z, f1.w, H.w, L.w);
            *reinterpret_cast<uint4*>(ph + j * 16) = H;
            *reinterpret_cast<uint4*>(pl + j * 16) = L;
        }
    } else if (row < 128) {
        char* ph = abuf + row * ROWB + q * 64;
        char* pl = ph + BUF_LO;
        uint4 Z = make_uint4(0, 0, 0, 0);
        #pragma unroll
        for (int j = 0; j < 4; ++j) {
            *reinterpret_cast<uint4*>(ph + j * 16) = Z;
            *reinterpret_cast<uint4*>(pl + j * 16) = Z;
        }
    }
}

// B tile fill (512 thr): 128 n x 128 k from pre-split weights (n-major, stride ldk)
__device__ __forceinline__ void fill_B(char* bbuf,
                                       const __nv_bfloat16* __restrict__ Whi,
                                       const __nv_bfloat16* __restrict__ Wlo,
                                       int k0, int ldk, int tid) {
    int n = tid >> 2, q = tid & 3;
    const __nv_bfloat16* ph = Whi + (size_t)n * ldk + k0 + q * 32;
    const __nv_bfloat16* pl = Wlo + (size_t)n * ldk + k0 + q * 32;
    char* dh = bbuf + n * ROWB + q * 64;
    char* dl = dh + BUF_LO;
    #pragma unroll
    for (int j = 0; j < 4; ++j) {
        *reinterpret_cast<uint4*>(dh + j * 16) = *reinterpret_cast<const uint4*>(ph + j * 8);
        *reinterpret_cast<uint4*>(dl + j * 16) = *reinterpret_cast<const uint4*>(pl + j * 8);
    }
}

// 3-pass 128x128x128 MMA; warp covers 32 rows x 32 cols. acc[2][4][4].
__device__ __forceinline__ void run_mma(uint32_t sa, uint32_t sbm, int lane,
                                        int warpm, int warpn, float acc[2][4][4]) {
    int g = lane >> 3;
    uint32_t arow = (warpm * 32 + (lane & 15)) * ROWB + (lane >> 4) * 16;
    uint32_t brow = (warpn * 32 + (g >> 1) * 8 + (lane & 7)) * ROWB + (g & 1) * 16;
    #pragma unroll
    for (int pass = 0; pass < 3; ++pass) {
        uint32_t abase = sa + ((pass == 2) ? BUF_LO : 0) + arow;
        uint32_t bbase = sbm + ((pass == 1) ? BUF_LO : 0) + brow;
        #pragma unroll
        for (int k = 0; k < 8; ++k) {
            uint32_t a0[4], a1[4], b[2][4];
            LDM4(a0, abase + k * 32);
            LDM4(a1, abase + 16 * ROWB + k * 32);
            LDM4(b[0], bbase + k * 32);
            LDM4(b[1], bbase + 16 * ROWB + k * 32);
            #pragma unroll
            for (int p = 0; p < 2; ++p) {
                mma16816(acc[0][2 * p],     a0, &b[p][0]);
                mma16816(acc[0][2 * p + 1], a0, &b[p][2]);
                mma16816(acc[1][2 * p],     a1, &b[p][0]);
                mma16816(acc[1][2 * p + 1], a1, &b[p][2]);
            }
        }
    }
}

#define ZERO_ACC(acc) { \
    _Pragma("unroll") for (int i = 0; i < 2; ++i) \
    _Pragma("unroll") for (int j = 0; j < 4; ++j) \
    _Pragma("unroll") for (int k = 0; k < 4; ++k) (acc)[i][j][k] = 0.f; }

// ------------------------- tiny kernels -------------------------------------
__global__ void k_zero(int n_nodes) {
    int i = blockIdx.x * blockDim.x + threadIdx.x;
    int tot4 = n_nodes * (D / 4);
    if (i < tot4) reinterpret_cast<float4*>(g_agg)[i] = make_float4(0.f, 0.f, 0.f, 0.f);
    if (i < n_nodes) g_deg[i] = 0.f;
}

__global__ void k_wprep(const float* __restrict__ We, const float* __restrict__ Wn) {
    int i = blockIdx.x * blockDim.x + threadIdx.x;
    if (i < 128 * 384) {
        float w = We[i];
        __nv_bfloat16 h = __float2bfloat16(w);
        g_We_hi[i] = h;
        g_We_lo[i] = __float2bfloat16(w - __bfloat162float(h));
    }
    if (i < 128 * 256) {
        float w = Wn[i];
        __nv_bfloat16 h = __float2bfloat16(w);
        g_Wn_hi[i] = h;
        g_Wn_lo[i] = __float2bfloat16(w - __bfloat162float(h));
    }
}

// ------------------------- main kernels -------------------------------------
// k_pre: multi-tile loop. grid=(G,2): half selects We col block; B staged once.
__global__ void __launch_bounds__(512, 1)
k_pre(const float* __restrict__ nf, const float* __restrict__ b_e, int N) {
    extern __shared__ char smem[];
    uint32_t sb = smem_u32(smem);
    int tid = threadIdx.x, lane = tid & 31, warp = tid >> 5;
    int warpm = warp & 3, warpn = warp >> 2;
    int half = blockIdx.y;
    int ntiles = (N + 127) >> 7;

    fill_B(smem + 2 * BUF_SZ, g_We_hi, g_We_lo, half * 128, 384, tid);

    int t = blockIdx.x, cur = 0;
    if (t < ntiles) fill_A(smem, nf, t * 128, min(128, N - t * 128), nullptr, tid);
    __syncthreads();

    int q = lane & 3, r4 = lane >> 2;
    while (t < ntiles) {
        float acc[2][4][4];
        ZERO_ACC(acc);
        run_mma(sb + cur * BUF_SZ, sb + 2 * BUF_SZ, lane, warpm, warpn, acc);

        int tn = t + gridDim.x;
        if (tn < ntiles)
            fill_A(smem + (cur ^ 1) * BUF_SZ, nf, tn * 128, min(128, N - tn * 128), nullptr, tid);

        int mbase = t * 128;
        #pragma unroll
        for (int mt = 0; mt < 2; ++mt)
            #pragma unroll
            for (int rh = 0; rh < 2; ++rh) {
                int m = mbase + warpm * 32 + mt * 16 + rh * 8 + r4;
                if (m < N) {
                    float* pd = g_AB + (size_t)m * 256 + half * 128;
                    #pragma unroll
                    for (int nt = 0; nt < 4; ++nt) {
                        int col = warpn * 32 + nt * 8 + q * 2;
                        float vx = acc[mt][nt][rh * 2 + 0];
                        float vy = acc[mt][nt][rh * 2 + 1];
                        if (half == 1) {
                            float2 bb = *reinterpret_cast<const float2*>(b_e + col);
                            vx += bb.x; vy += bb.y;
                        }
                        *reinterpret_cast<float2*>(pd + col) = make_float2(vx, vy);
                    }
                }
            }
        __syncthreads();
        cur ^= 1; t = tn;
    }
}

// k_edge: multi-tile loop; B (We cols 256:384) staged once; A double-buffered.
__global__ void __launch_bounds__(512, 1)
k_edge(const float* __restrict__ ef, const int* __restrict__ src,
       const int* __restrict__ dst, float* __restrict__ e_out, int E) {
    extern __shared__ char smem[];
    uint32_t sb = smem_u32(smem);
    int tid = threadIdx.x, lane = tid & 31, warp = tid >> 5;
    int warpm = warp & 3, warpn = warp >> 2;
    int ntiles = E >> 7;                       // E % 128 == 0

    fill_B(smem + 2 * BUF_SZ, g_We_hi, g_We_lo, 256, 384, tid);

    int t = blockIdx.x, cur = 0;
    if (t < ntiles) fill_A(smem, ef, t * 128, 128, nullptr, tid);
    __syncthreads();

    int q = lane & 3, r4 = lane >> 2;
    while (t < ntiles) {
        float acc[2][4][4];
        ZERO_ACC(acc);
        run_mma(sb + cur * BUF_SZ, sb + 2 * BUF_SZ, lane, warpm, warpn, acc);

        int tn = t + gridDim.x;
        if (tn < ntiles) fill_A(smem + (cur ^ 1) * BUF_SZ, ef, tn * 128, 128, nullptr, tid);

        int mbase = t * 128;
        #pragma unroll
        for (int mt = 0; mt < 2; ++mt)
            #pragma unroll
            for (int rh = 0; rh < 2; ++rh) {
                int rl = warpm * 32 + mt * 16 + rh * 8 + r4;
                int m = mbase + rl;
                int s = __ldg(src + m), d2 = __ldg(dst + m);
                const float* pA = g_AB + (size_t)s * 256;
                const float* pB = g_AB + (size_t)d2 * 256 + 128;
                float* pe = e_out + (size_t)m * D;
                float* pg = g_agg + (size_t)d2 * D;
                #pragma unroll
                for (int nt = 0; nt < 4; ++nt) {
                    int col = warpn * 32 + nt * 8 + q * 2;
                    float2 av = *reinterpret_cast<const float2*>(pA + col);
                    float2 bv = *reinterpret_cast<const float2*>(pB + col);
                    float vx = acc[mt][nt][rh * 2 + 0] + av.x + bv.x;
                    float vy = acc[mt][nt][rh * 2 + 1] + av.y + bv.y;
                    *reinterpret_cast<float2*>(pe + col) = make_float2(vx, vy);
                    asm volatile("red.global.add.v2.f32 [%0], {%1,%2};"
                                 :: "l"(pg + col), "f"(vx), "f"(vy) : "memory");
                }
                if (q == 0 && warpn == 0) atomicAdd(&g_deg[d2], 1.0f);
            }
        __syncthreads();
        cur ^= 1; t = tn;
    }
}

// k_node: one tile per CTA; B0/B1 staged; A refilled between stages.
__global__ void __launch_bounds__(512, 1)
k_node(const float* __restrict__ nf, const float* __restrict__ b_n,
       float* __restrict__ n_out, int N) {
    extern __shared__ char smem[];
    uint32_t sb = smem_u32(smem);
    int tid = threadIdx.x, lane = tid & 31, warp = tid >> 5;
    int warpm = warp & 3, warpn = warp >> 2;
    int mbase = blockIdx.x * 128;
    int nrows = min(128, N - mbase);

    fill_B(smem + BUF_SZ, g_Wn_hi, g_Wn_lo, 0, 256, tid);
    fill_B(smem + 2 * BUF_SZ, g_Wn_hi, g_Wn_lo, 128, 256, tid);
    fill_A(smem, nf, mbase, nrows, nullptr, tid);
    __syncthreads();

    float acc[2][4][4];
    ZERO_ACC(acc);
    run_mma(sb, sb + BUF_SZ, lane, warpm, warpn, acc);
    __syncthreads();

    fill_A(smem, g_agg, mbase, nrows, g_deg, tid);
    __syncthreads();
    run_mma(sb, sb + 2 * BUF_SZ, lane, warpm, warpn, acc);

    int q = lane & 3, r4 = lane >> 2;
    #pragma unroll
    for (int mt = 0; mt < 2; ++mt)
        #pragma unroll
        for (int rh = 0; rh < 2; ++rh) {
            int m = mbase + warpm * 32 + mt * 16 + rh * 8 + r4;
            if (m < N) {
                float* pd = n_out + (size_t)m * D;
                #pragma unroll
                for (int nt = 0; nt < 4; ++nt) {
                    int col = warpn * 32 + nt * 8 + q * 2;
                    float2 bb = *reinterpret_cast<const float2*>(b_n + col);
                    *reinterpret_cast<float2*>(pd + col) =
                        make_float2(acc[mt][nt][rh * 2 + 0] + bb.x,
                                    acc[mt][nt][rh * 2 + 1] + bb.y);
                }
            }
        }
}

// ---------------------------------------------------------------------------
extern "C" void kernel_launch(void* const* d_in, const int* in_sizes, int n_in,
                              void* d_out, int out_size) {
    const float* nf  = (const float*)d_in[0];
    const float* ef  = (const float*)d_in[1];
    const int*   src = (const int*)d_in[2];   // int32 (JAX x64 disabled)
    const int*   dst = (const int*)d_in[3];
    const float* We  = (const float*)d_in[4];
    const float* be  = (const float*)d_in[5];
    const float* Wn  = (const float*)d_in[6];
    const float* bn  = (const float*)d_in[7];

    int N = in_sizes[0] / D;
    int E = in_sizes[1] / D;

    float* n_out = (float*)d_out;
    float* e_out = n_out + (size_t)N * D;

    cudaFuncSetAttribute(k_pre,  cudaFuncAttributeMaxDynamicSharedMemorySize, SMEM_BYTES);
    cudaFuncSetAttribute(k_edge, cudaFuncAttributeMaxDynamicSharedMemorySize, SMEM_BYTES);
    cudaFuncSetAttribute(k_node, cudaFuncAttributeMaxDynamicSharedMemorySize, SMEM_BYTES);

    int zthreads = N * (D / 4);
    k_zero<<<(zthreads + 255) / 256, 256>>>(N);
    k_wprep<<<(128 * 384 + 255) / 256, 256>>>(We, Wn);

    dim3 gpre(148, 2);
    k_pre<<<gpre, 512, SMEM_BYTES>>>(nf, be, N);
    k_edge<<<148, 512, SMEM_BYTES>>>(ef, src, dst, e_out, E);
    k_node<<<(N + 127) / 128, 512, SMEM_BYTES>>>(nf, bn, n_out, N);
}

// round 6
// speedup vs baseline: 1.4962x; 1.4962x over previous
#include <cuda_runtime.h>
#include <cuda_bf16.h>
#include <cstdint>

#define D 128
#define MAXN 40000

// ------------------------- device scratch (no allocs) -----------------------
__device__ __align__(16) float g_AB[(size_t)MAXN * 256]; // [N][256]: A=nf@W1^T | B'=nf@W2^T+b_e
__device__ __align__(16) float g_agg[(size_t)MAXN * D];
__device__ __align__(16) float g_deg[MAXN];
// Fragment-packed weights: [5 blocks][2 planes][8 ks][8 npair][32 lane] uint4
// block: 0=We[:,0:128] 1=We[:,128:256] 2=We[:,256:384] 3=Wn[:,0:128] 4=Wn[:,128:256]
__device__ __align__(16) uint4 g_pk[5 * 2 * 2048];

// ------------------------- smem layout --------------------------------------
#define ROWB 272                  // 136 bf16/row: 4-bank shift/row, LDSM conflict-free
#define A_LO_OFF 17408            // 64*272
#define A_BUF 34816               // hi+lo planes for 64 rows
#define STG_OFF 34816             // k_edge acc staging
#define STG_STRIDE 132            // floats; 4-bank shift/row
#define SMEM_EDGE (34816 + 64 * STG_STRIDE * 4)   // 68608
#define SMEM_SMALL 34816

__device__ __forceinline__ uint32_t smem_u32(const void* p) {
    uint32_t a;
    asm("{ .reg .u64 t; cvta.to.shared.u64 t, %1; cvt.u32.u64 %0, t; }" : "=r"(a) : "l"(p));
    return a;
}

#define LDM4(r, addr) \
    asm volatile("ldmatrix.sync.aligned.m8n8.x4.shared.b16 {%0,%1,%2,%3}, [%4];" \
        : "=r"((r)[0]), "=r"((r)[1]), "=r"((r)[2]), "=r"((r)[3]) : "r"(addr))

__device__ __forceinline__ void mma16816(float* c, const uint32_t* a, uint32_t b0, uint32_t b1) {
    asm volatile("mma.sync.aligned.m16n8k16.row.col.f32.bf16.bf16.f32 "
        "{%0,%1,%2,%3}, {%4,%5,%6,%7}, {%8,%9}, {%0,%1,%2,%3};"
        : "+f"(c[0]), "+f"(c[1]), "+f"(c[2]), "+f"(c[3])
        : "r"(a[0]), "r"(a[1]), "r"(a[2]), "r"(a[3]), "r"(b0), "r"(b1));
}

__device__ __forceinline__ void split2(float x, float y, uint32_t& h, uint32_t& l) {
    __nv_bfloat162 hh = __floats2bfloat162_rn(x, y);
    __nv_bfloat162 ll = __floats2bfloat162_rn(x - __bfloat162float(hh.x),
                                              y - __bfloat162float(hh.y));
    h = *reinterpret_cast<uint32_t*>(&hh);
    l = *reinterpret_cast<uint32_t*>(&ll);
}

// ---- A tile: prefetch 64x128 fp32 to regs, then convert+STS -----------------
struct ARegs { float4 r[8]; };

__device__ __forceinline__ void load_A(ARegs& R, const float* __restrict__ g,
                                       int row0, int nrows, int tid) {
    int row = tid >> 2, q = tid & 3;
    if (row < nrows) {
        const float* gr = g + (size_t)(row0 + row) * D + q * 32;
        #pragma unroll
        for (int j = 0; j < 8; ++j) R.r[j] = __ldg(reinterpret_cast<const float4*>(gr) + j);
    } else {
        #pragma unroll
        for (int j = 0; j < 8; ++j) R.r[j] = make_float4(0.f, 0.f, 0.f, 0.f);
    }
}

__device__ __forceinline__ void sts_A(char* abuf, const ARegs& R, float s, int tid) {
    int row = tid >> 2, q = tid & 3;
    char* ph = abuf + row * ROWB + q * 64;
    #pragma unroll
    for (int jj = 0; jj < 4; ++jj) {
        float4 f0 = R.r[2 * jj], f1 = R.r[2 * jj + 1];
        f0.x *= s; f0.y *= s; f0.z *= s; f0.w *= s;
        f1.x *= s; f1.y *= s; f1.z *= s; f1.w *= s;
        uint4 H, L;
        split2(f0.x, f0.y, H.x, L.x);
        split2(f0.z, f0.w, H.y, L.y);
        split2(f1.x, f1.y, H.z, L.z);
        split2(f1.z, f1.w, H.w, L.w);
        *reinterpret_cast<uint4*>(ph + jj * 16) = H;
        *reinterpret_cast<uint4*>(ph + A_LO_OFF + jj * 16) = L;
    }
}

// ---- 3-pass 64x128x128 MMA: A from smem (LDSM), B from packed gmem (L1) -----
__device__ __forceinline__ void run_mma(uint32_t sa, int block, int warpm, int warpn,
                                        int lane, float acc[2][4][4]) {
    uint32_t arow = sa + (warpm * 32 + (lane & 15)) * ROWB + (lane >> 4) * 16;
    const uint4* __restrict__ Bb = g_pk + (size_t)block * 2 * 2048;
    int boff = warpn * 64 + lane;
    #pragma unroll
    for (int pass = 0; pass < 3; ++pass) {
        uint32_t abase = arow + ((pass == 2) ? A_LO_OFF : 0);
        const uint4* __restrict__ B = Bb + ((pass == 1) ? 2048 : 0);
        #pragma unroll
        for (int ks = 0; ks < 8; ++ks) {
            uint32_t a0[4], a1[4];
            LDM4(a0, abase + ks * 32);
            LDM4(a1, abase + 16 * ROWB + ks * 32);
            uint4 U0 = __ldg(B + ks * 256 + boff);
            uint4 U1 = __ldg(B + ks * 256 + boff + 32);
            mma16816(acc[0][0], a0, U0.x, U0.y);
            mma16816(acc[0][1], a0, U0.z, U0.w);
            mma16816(acc[0][2], a0, U1.x, U1.y);
            mma16816(acc[0][3], a0, U1.z, U1.w);
            mma16816(acc[1][0], a1, U0.x, U0.y);
            mma16816(acc[1][1], a1, U0.z, U0.w);
            mma16816(acc[1][2], a1, U1.x, U1.y);
            mma16816(acc[1][3], a1, U1.z, U1.w);
        }
    }
}

#define ZERO_ACC(acc) { \
    _Pragma("unroll") for (int i_ = 0; i_ < 2; ++i_) \
    _Pragma("unroll") for (int j_ = 0; j_ < 4; ++j_) \
    _Pragma("unroll") for (int k_ = 0; k_ < 4; ++k_) (acc)[i_][j_][k_] = 0.f; }

// ------------------------- tiny kernels -------------------------------------
__global__ void k_zero(int n_nodes) {
    int i = blockIdx.x * blockDim.x + threadIdx.x;
    int tot4 = n_nodes * (D / 4);
    if (i < tot4) reinterpret_cast<float4*>(g_agg)[i] = make_float4(0.f, 0.f, 0.f, 0.f);
    if (i < n_nodes) g_deg[i] = 0.f;
}

// pack weights into mma-fragment order, hi/lo planes
__global__ void k_wprep(const float* __restrict__ We, const float* __restrict__ Wn) {
    int idx = blockIdx.x * blockDim.x + threadIdx.x;
    if (idx >= 5 * 2 * 2048) return;
    int lane = idx & 31, npair = (idx >> 5) & 7, ks = (idx >> 8) & 7;
    int plane = (idx >> 11) & 1, b = idx >> 12;
    const float* W;
    int colbase, ldk;
    if (b < 3) { W = We; ldk = 384; colbase = b * 128; }
    else       { W = Wn; ldk = 256; colbase = (b - 3) * 128; }
    uint32_t out[4];
    #pragma unroll
    for (int j = 0; j < 4; ++j) {
        int n = (npair * 2 + (j >> 1)) * 8 + (lane >> 2);
        int k = ks * 16 + (lane & 3) * 2 + (j & 1) * 8;
        float w0 = W[(size_t)n * ldk + colbase + k];
        float w1 = W[(size_t)n * ldk + colbase + k + 1];
        __nv_bfloat16 h0 = __float2bfloat16(w0), h1 = __float2bfloat16(w1);
        __nv_bfloat162 v;
        if (plane) {
            v.x = __float2bfloat16(w0 - __bfloat162float(h0));
            v.y = __float2bfloat16(w1 - __bfloat162float(h1));
        } else { v.x = h0; v.y = h1; }
        out[j] = *reinterpret_cast<uint32_t*>(&v);
    }
    g_pk[idx] = make_uint4(out[0], out[1], out[2], out[3]);
}

// ------------------------- main kernels -------------------------------------
// k_pre: persistent, grid (G,2). half -> g_AB cols [half*128, +128)
__global__ void __launch_bounds__(256, 2)
k_pre(const float* __restrict__ nf, const float* __restrict__ b_e, int N) {
    extern __shared__ char smem[];
    uint32_t sa = smem_u32(smem);
    int tid = threadIdx.x, lane = tid & 31, warp = tid >> 5;
    int warpm = warp >> 2, warpn = warp & 3;
    int half = blockIdx.y;
    int ntiles = (N + 63) >> 6;
    int q = lane & 3, r4 = lane >> 2;

    int t = blockIdx.x;
    if (t >= ntiles) return;
    ARegs R;
    load_A(R, nf, t * 64, min(64, N - t * 64), tid);

    while (t < ntiles) {
        sts_A(smem, R, 1.f, tid);
        __syncthreads();
        int tn = t + gridDim.x;
        if (tn < ntiles) load_A(R, nf, tn * 64, min(64, N - tn * 64), tid);

        float acc[2][4][4];
        ZERO_ACC(acc);
        run_mma(sa, half, warpm, warpn, lane, acc);

        int mbase = t * 64;
        #pragma unroll
        for (int i = 0; i < 2; ++i)
            #pragma unroll
            for (int rh = 0; rh < 2; ++rh) {
                int m = mbase + warpm * 32 + i * 16 + rh * 8 + r4;
                if (m < N) {
                    float* pd = g_AB + (size_t)m * 256 + half * 128;
                    #pragma unroll
                    for (int nt = 0; nt < 4; ++nt) {
                        int col = warpn * 32 + nt * 8 + q * 2;
                        float vx = acc[i][nt][rh * 2 + 0];
                        float vy = acc[i][nt][rh * 2 + 1];
                        if (half == 1) {
                            float2 bb = *reinterpret_cast<const float2*>(b_e + col);
                            vx += bb.x; vy += bb.y;
                        }
                        *reinterpret_cast<float2*>(pd + col) = make_float2(vx, vy);
                    }
                }
            }
        __syncthreads();
        t = tn;
    }
}

// k_edge: persistent; staged coalesced epilogue with gather + scatter-red
__global__ void __launch_bounds__(256, 2)
k_edge(const float* __restrict__ ef, const int* __restrict__ src,
       const int* __restrict__ dst, float* __restrict__ e_out, int E) {
    extern __shared__ char smem[];
    uint32_t sa = smem_u32(smem);
    float* stage = reinterpret_cast<float*>(smem + STG_OFF);
    int tid = threadIdx.x, lane = tid & 31, warp = tid >> 5;
    int warpm = warp >> 2, warpn = warp & 3;
    int ntiles = E >> 6;
    int q = lane & 3, r4 = lane >> 2;

    int t = blockIdx.x;
    if (t >= ntiles) return;
    ARegs R;
    load_A(R, ef, t * 64, 64, tid);

    while (t < ntiles) {
        sts_A(smem, R, 1.f, tid);
        __syncthreads();
        int tn = t + gridDim.x;
        if (tn < ntiles) load_A(R, ef, tn * 64, 64, tid);

        float acc[2][4][4];
        ZERO_ACC(acc);
        run_mma(sa, 2, warpm, warpn, lane, acc);

        // stage acc -> smem for row-coalesced epilogue
        #pragma unroll
        for (int i = 0; i < 2; ++i)
            #pragma unroll
            for (int rh = 0; rh < 2; ++rh) {
                int rl = warpm * 32 + i * 16 + rh * 8 + r4;
                #pragma unroll
                for (int nt = 0; nt < 4; ++nt) {
                    int col = warpn * 32 + nt * 8 + q * 2;
                    *reinterpret_cast<float2*>(stage + rl * STG_STRIDE + col) =
                        make_float2(acc[i][nt][rh * 2 + 0], acc[i][nt][rh * 2 + 1]);
                }
            }
        __syncthreads();

        // each warp owns 8 full rows: fully coalesced gathers/stores/reds
        int mbase = t * 64;
        #pragma unroll
        for (int r = 0; r < 8; ++r) {
            int rl = warp * 8 + r;
            int m = mbase + rl;
            int s = __ldg(src + m), d2 = __ldg(dst + m);
            float4 st = *reinterpret_cast<const float4*>(stage + rl * STG_STRIDE + lane * 4);
            float4 a = __ldg(reinterpret_cast<const float4*>(g_AB + (size_t)s * 256) + lane);
            float4 b = __ldg(reinterpret_cast<const float4*>(g_AB + (size_t)d2 * 256 + 128) + lane);
            float4 v = make_float4(st.x + a.x + b.x, st.y + a.y + b.y,
                                   st.z + a.z + b.z, st.w + a.w + b.w);
            reinterpret_cast<float4*>(e_out + (size_t)m * D)[lane] = v;
            float* pg = g_agg + (size_t)d2 * D + lane * 4;
            asm volatile("red.global.add.v4.f32 [%0], {%1,%2,%3,%4};"
                         :: "l"(pg), "f"(v.x), "f"(v.y), "f"(v.z), "f"(v.w) : "memory");
            if (lane == 0) atomicAdd(&g_deg[d2], 1.0f);
        }
        __syncthreads();
        t = tn;
    }
}

// k_node: persistent; two K-stages (nf, agg/deg) accumulate, then +b_n
__global__ void __launch_bounds__(256, 2)
k_node(const float* __restrict__ nf, const float* __restrict__ b_n,
       float* __restrict__ n_out, int N) {
    extern __shared__ char smem[];
    uint32_t sa = smem_u32(smem);
    int tid = threadIdx.x, lane = tid & 31, warp = tid >> 5;
    int warpm = warp >> 2, warpn = warp & 3;
    int ntiles = (N + 63) >> 6;
    int q = lane & 3, r4 = lane >> 2;

    for (int t = blockIdx.x; t < ntiles; t += gridDim.x) {
        int mbase = t * 64;
        int nrows = min(64, N - mbase);

        ARegs R;
        load_A(R, nf, mbase, nrows, tid);
        sts_A(smem, R, 1.f, tid);
        __syncthreads();

        float acc[2][4][4];
        ZERO_ACC(acc);
        run_mma(sa, 3, warpm, warpn, lane, acc);
        __syncthreads();

        // stage 2: agg/deg
        int row = tid >> 2;
        float s = 1.f;
        if (row < nrows) s = 1.f / fmaxf(__ldg(g_deg + mbase + row), 1.f);
        load_A(R, g_agg, mbase, nrows, tid);
        sts_A(smem, R, s, tid);
        __syncthreads();
        run_mma(sa, 4, warpm, warpn, lane, acc);

        #pragma unroll
        for (int i = 0; i < 2; ++i)
            #pragma unroll
            for (int rh = 0; rh < 2; ++rh) {
                int m = mbase + warpm * 32 + i * 16 + rh * 8 + r4;
                if (m < N) {
                    float* pd = n_out + (size_t)m * D;
                    #pragma unroll
                    for (int nt = 0; nt < 4; ++nt) {
                        int col = warpn * 32 + nt * 8 + q * 2;
                        float2 bb = *reinterpret_cast<const float2*>(b_n + col);
                        *reinterpret_cast<float2*>(pd + col) =
                            make_float2(acc[i][nt][rh * 2 + 0] + bb.x,
                                        acc[i][nt][rh * 2 + 1] + bb.y);
                    }
                }
            }
        __syncthreads();
    }
}

// ---------------------------------------------------------------------------
extern "C" void kernel_launch(void* const* d_in, const int* in_sizes, int n_in,
                              void* d_out, int out_size) {
    const float* nf  = (const float*)d_in[0];
    const float* ef  = (const float*)d_in[1];
    const int*   src = (const int*)d_in[2];   // int32 (JAX x64 disabled)
    const int*   dst = (const int*)d_in[3];
    const float* We  = (const float*)d_in[4];
    const float* be  = (const float*)d_in[5];
    const float* Wn  = (const float*)d_in[6];
    const float* bn  = (const float*)d_in[7];

    int N = in_sizes[0] / D;
    int E = in_sizes[1] / D;

    float* n_out = (float*)d_out;
    float* e_out = n_out + (size_t)N * D;

    cudaFuncSetAttribute(k_pre,  cudaFuncAttributeMaxDynamicSharedMemorySize, SMEM_SMALL);
    cudaFuncSetAttribute(k_edge, cudaFuncAttributeMaxDynamicSharedMemorySize, SMEM_EDGE);
    cudaFuncSetAttribute(k_node, cudaFuncAttributeMaxDynamicSharedMemorySize, SMEM_SMALL);

    int zthreads = N * (D / 4);
    k_zero<<<(zthreads + 255) / 256, 256>>>(N);
    k_wprep<<<(5 * 2 * 2048 + 255) / 256, 256>>>(We, Wn);

    dim3 gpre(296, 2);
    k_pre<<<gpre, 256, SMEM_SMALL>>>(nf, be, N);
    k_edge<<<296, 256, SMEM_EDGE>>>(ef, src, dst, e_out, E);
    k_node<<<296, 256, SMEM_SMALL>>>(nf, bn, n_out, N);
}

// round 7
// speedup vs baseline: 1.5899x; 1.0626x over previous
#include <cuda_runtime.h>
#include <cuda_bf16.h>
#include <cstdint>

#define D 128
#define MAXN 40000

// ------------------------- device scratch (no allocs) -----------------------
__device__ __align__(16) float g_AB[(size_t)MAXN * 256]; // [N][256]: A=nf@W1^T | B'=nf@W2^T+b_e
__device__ __align__(16) float g_agg[(size_t)MAXN * D];
__device__ __align__(16) float g_deg[MAXN];
// Fragment-packed weights: [5 blocks][2 planes][8 ks][8 npair][32 lane] uint4
// block: 0=We[:,0:128] 1=We[:,128:256] 2=We[:,256:384] 3=Wn[:,0:128] 4=Wn[:,128:256]
__device__ __align__(16) uint4 g_pk[5 * 2 * 2048];

// ------------------------- smem layout --------------------------------------
#define ROWB 272                  // 136 bf16/row: 4-bank shift/row, LDSM conflict-free
#define A_LO_OFF 17408            // 64*272
#define STG_OFF 34816             // k_edge acc staging
#define STG_STRIDE 132
#define SMEM_EDGE (34816 + 64 * STG_STRIDE * 4)   // 68608
#define SMEM_SMALL 34816

__device__ __forceinline__ uint32_t smem_u32(const void* p) {
    uint32_t a;
    asm("{ .reg .u64 t; cvta.to.shared.u64 t, %1; cvt.u32.u64 %0, t; }" : "=r"(a) : "l"(p));
    return a;
}

#define LDM4(r, addr) \
    asm volatile("ldmatrix.sync.aligned.m8n8.x4.shared.b16 {%0,%1,%2,%3}, [%4];" \
        : "=r"((r)[0]), "=r"((r)[1]), "=r"((r)[2]), "=r"((r)[3]) : "r"(addr))

__device__ __forceinline__ void mma16816(float* c, const uint32_t* a, uint32_t b0, uint32_t b1) {
    asm volatile("mma.sync.aligned.m16n8k16.row.col.f32.bf16.bf16.f32 "
        "{%0,%1,%2,%3}, {%4,%5,%6,%7}, {%8,%9}, {%0,%1,%2,%3};"
        : "+f"(c[0]), "+f"(c[1]), "+f"(c[2]), "+f"(c[3])
        : "r"(a[0]), "r"(a[1]), "r"(a[2]), "r"(a[3]), "r"(b0), "r"(b1));
}

__device__ __forceinline__ void split2(float x, float y, uint32_t& h, uint32_t& l) {
    __nv_bfloat162 hh = __floats2bfloat162_rn(x, y);
    __nv_bfloat162 ll = __floats2bfloat162_rn(x - __bfloat162float(hh.x),
                                              y - __bfloat162float(hh.y));
    h = *reinterpret_cast<uint32_t*>(&hh);
    l = *reinterpret_cast<uint32_t*>(&ll);
}

__device__ __forceinline__ void cvt_store(char* ph, float4 f0, float4 f1, int jj, float s) {
    f0.x *= s; f0.y *= s; f0.z *= s; f0.w *= s;
    f1.x *= s; f1.y *= s; f1.z *= s; f1.w *= s;
    uint4 H, L;
    split2(f0.x, f0.y, H.x, L.x);
    split2(f0.z, f0.w, H.y, L.y);
    split2(f1.x, f1.y, H.z, L.z);
    split2(f1.z, f1.w, H.w, L.w);
    *reinterpret_cast<uint4*>(ph + jj * 16) = H;
    *reinterpret_cast<uint4*>(ph + A_LO_OFF + jj * 16) = L;
}

// ---- 8-mma block helper -----------------------------------------------------
__device__ __forceinline__ void mma8(float acc[2][4][4], const uint32_t* a0,
                                     const uint32_t* a1, uint4 U0, uint4 U1) {
    mma16816(acc[0][0], a0, U0.x, U0.y);
    mma16816(acc[0][1], a0, U0.z, U0.w);
    mma16816(acc[0][2], a0, U1.x, U1.y);
    mma16816(acc[0][3], a0, U1.z, U1.w);
    mma16816(acc[1][0], a1, U0.x, U0.y);
    mma16816(acc[1][1], a1, U0.z, U0.w);
    mma16816(acc[1][2], a1, U1.x, U1.y);
    mma16816(acc[1][3], a1, U1.z, U1.w);
}

// 3-pass MMA, B_hi from persistent regs, B_lo from L1, a_hi LDSM reused
__device__ __forceinline__ void run_mma_breg(uint32_t sa, const uint4* bh,
                                             const uint4* __restrict__ Blo, int boff,
                                             int warpm, int lane, float acc[2][4][4]) {
    uint32_t arow = sa + (warpm * 32 + (lane & 15)) * ROWB + (lane >> 4) * 16;
    #pragma unroll
    for (int ks = 0; ks < 8; ++ks) {
        uint32_t a0[4], a1[4], c0[4], c1[4];
        uint4 V0 = __ldg(Blo + ks * 256 + boff);
        uint4 V1 = __ldg(Blo + ks * 256 + boff + 32);
        LDM4(a0, arow + ks * 32);
        LDM4(a1, arow + 16 * ROWB + ks * 32);
        uint4 U0 = bh[2 * ks], U1 = bh[2 * ks + 1];
        mma8(acc, a0, a1, U0, U1);                       // hi x hi
        mma8(acc, a0, a1, V0, V1);                       // hi x lo
        LDM4(c0, arow + A_LO_OFF + ks * 32);
        LDM4(c1, arow + A_LO_OFF + 16 * ROWB + ks * 32);
        mma8(acc, c0, c1, U0, U1);                       // lo x hi
    }
}

// legacy 3-pass (B fully from gmem) for k_node
__device__ __forceinline__ void run_mma(uint32_t sa, int block, int warpm, int warpn,
                                        int lane, float acc[2][4][4]) {
    uint32_t arow = sa + (warpm * 32 + (lane & 15)) * ROWB + (lane >> 4) * 16;
    const uint4* __restrict__ Bb = g_pk + (size_t)block * 2 * 2048;
    int boff = warpn * 64 + lane;
    #pragma unroll
    for (int ks = 0; ks < 8; ++ks) {
        uint32_t a0[4], a1[4], c0[4], c1[4];
        uint4 U0 = __ldg(Bb + ks * 256 + boff);
        uint4 U1 = __ldg(Bb + ks * 256 + boff + 32);
        uint4 V0 = __ldg(Bb + 2048 + ks * 256 + boff);
        uint4 V1 = __ldg(Bb + 2048 + ks * 256 + boff + 32);
        LDM4(a0, arow + ks * 32);
        LDM4(a1, arow + 16 * ROWB + ks * 32);
        mma8(acc, a0, a1, U0, U1);
        mma8(acc, a0, a1, V0, V1);
        LDM4(c0, arow + A_LO_OFF + ks * 32);
        LDM4(c1, arow + A_LO_OFF + 16 * ROWB + ks * 32);
        mma8(acc, c0, c1, U0, U1);
    }
}

#define ZERO_ACC(acc) { \
    _Pragma("unroll") for (int i_ = 0; i_ < 2; ++i_) \
    _Pragma("unroll") for (int j_ = 0; j_ < 4; ++j_) \
    _Pragma("unroll") for (int k_ = 0; k_ < 4; ++k_) (acc)[i_][j_][k_] = 0.f; }

// ------------------------- tiny kernels -------------------------------------
__global__ void k_zero(int n_nodes) {
    int i = blockIdx.x * blockDim.x + threadIdx.x;
    int tot4 = n_nodes * (D / 4);
    if (i < tot4) reinterpret_cast<float4*>(g_agg)[i] = make_float4(0.f, 0.f, 0.f, 0.f);
    if (i < n_nodes) g_deg[i] = 0.f;
}

__global__ void k_wprep(const float* __restrict__ We, const float* __restrict__ Wn) {
    int idx = blockIdx.x * blockDim.x + threadIdx.x;
    if (idx >= 5 * 2 * 2048) return;
    int lane = idx & 31, npair = (idx >> 5) & 7, ks = (idx >> 8) & 7;
    int plane = (idx >> 11) & 1, b = idx >> 12;
    const float* W;
    int colbase, ldk;
    if (b < 3) { W = We; ldk = 384; colbase = b * 128; }
    else       { W = Wn; ldk = 256; colbase = (b - 3) * 128; }
    uint32_t out[4];
    #pragma unroll
    for (int j = 0; j < 4; ++j) {
        int n = (npair * 2 + (j >> 1)) * 8 + (lane >> 2);
        int k = ks * 16 + (lane & 3) * 2 + (j & 1) * 8;
        float w0 = W[(size_t)n * ldk + colbase + k];
        float w1 = W[(size_t)n * ldk + colbase + k + 1];
        __nv_bfloat16 h0 = __float2bfloat16(w0), h1 = __float2bfloat16(w1);
        __nv_bfloat162 v;
        if (plane) {
            v.x = __float2bfloat16(w0 - __bfloat162float(h0));
            v.y = __float2bfloat16(w1 - __bfloat162float(h1));
        } else { v.x = h0; v.y = h1; }
        out[j] = *reinterpret_cast<uint32_t*>(&v);
    }
    g_pk[idx] = make_uint4(out[0], out[1], out[2], out[3]);
}

// ------------------------- main kernels -------------------------------------
// k_pre: persistent, grid (G,2); Bhi regs; nf cached normally (reused later)
__global__ void __launch_bounds__(256, 2)
k_pre(const float* __restrict__ nf, const float* __restrict__ b_e, int N) {
    extern __shared__ char smem[];
    uint32_t sa = smem_u32(smem);
    int tid = threadIdx.x, lane = tid & 31, warp = tid >> 5;
    int warpm = warp >> 2, warpn = warp & 3;
    int half = blockIdx.y;
    int ntiles = (N + 63) >> 6;
    int q = lane & 3, r4 = lane >> 2;
    int row = tid >> 2, qq = tid & 3;

    const uint4* __restrict__ Bb = g_pk + (size_t)half * 2 * 2048;
    const uint4* __restrict__ Blo = Bb + 2048;
    int boff = warpn * 64 + lane;
    uint4 bh[16];
    #pragma unroll
    for (int ks = 0; ks < 8; ++ks) {
        bh[2 * ks] = __ldg(Bb + ks * 256 + boff);
        bh[2 * ks + 1] = __ldg(Bb + ks * 256 + boff + 32);
    }

    int t = blockIdx.x;
    if (t >= ntiles) return;

    float4 P[4];
    {
        bool v = t * 64 + row < N;
        const float4* gr = reinterpret_cast<const float4*>(nf + (size_t)(t * 64 + row) * D + qq * 32);
        #pragma unroll
        for (int j = 0; j < 4; ++j)
            P[j] = v ? __ldg(gr + j) : make_float4(0.f, 0.f, 0.f, 0.f);
    }

    while (t < ntiles) {
        {   // fill A: prefetched half + direct half
            bool v = t * 64 + row < N;
            const float4* gr = reinterpret_cast<const float4*>(nf + (size_t)(t * 64 + row) * D + qq * 32);
            float4 Dq[4];
            #pragma unroll
            for (int j = 0; j < 4; ++j)
                Dq[j] = v ? __ldg(gr + 4 + j) : make_float4(0.f, 0.f, 0.f, 0.f);
            char* ph = smem + row * ROWB + qq * 64;
            cvt_store(ph, P[0], P[1], 0, 1.f);
            cvt_store(ph, P[2], P[3], 1, 1.f);
            cvt_store(ph, Dq[0], Dq[1], 2, 1.f);
            cvt_store(ph, Dq[2], Dq[3], 3, 1.f);
        }
        __syncthreads();
        int tn = t + gridDim.x;
        if (tn < ntiles) {
            bool v = tn * 64 + row < N;
            const float4* gr = reinterpret_cast<const float4*>(nf + (size_t)(tn * 64 + row) * D + qq * 32);
            #pragma unroll
            for (int j = 0; j < 4; ++j)
                P[j] = v ? __ldg(gr + j) : make_float4(0.f, 0.f, 0.f, 0.f);
        }

        float acc[2][4][4];
        ZERO_ACC(acc);
        run_mma_breg(sa, bh, Blo, boff, warpm, lane, acc);

        int mbase = t * 64;
        #pragma unroll
        for (int i = 0; i < 2; ++i)
            #pragma unroll
            for (int rh = 0; rh < 2; ++rh) {
                int m = mbase + warpm * 32 + i * 16 + rh * 8 + r4;
                if (m < N) {
                    float* pd = g_AB + (size_t)m * 256 + half * 128;
                    #pragma unroll
                    for (int nt = 0; nt < 4; ++nt) {
                        int col = warpn * 32 + nt * 8 + q * 2;
                        float vx = acc[i][nt][rh * 2 + 0];
                        float vy = acc[i][nt][rh * 2 + 1];
                        if (half == 1) {
                            float2 bb = *reinterpret_cast<const float2*>(b_e + col);
                            vx += bb.x; vy += bb.y;
                        }
                        *reinterpret_cast<float2*>(pd + col) = make_float2(vx, vy);
                    }
                }
            }
        __syncthreads();
        t = tn;
    }
}

// k_edge: persistent; Bhi regs; streaming cache hints; staged coalesced epilogue
__global__ void __launch_bounds__(256, 2)
k_edge(const float* __restrict__ ef, const int* __restrict__ src,
       const int* __restrict__ dst, float* __restrict__ e_out, int E) {
    extern __shared__ char smem[];
    uint32_t sa = smem_u32(smem);
    float* stage = reinterpret_cast<float*>(smem + STG_OFF);
    int tid = threadIdx.x, lane = tid & 31, warp = tid >> 5;
    int warpm = warp >> 2, warpn = warp & 3;
    int ntiles = E >> 6;
    int q = lane & 3, r4 = lane >> 2;
    int row = tid >> 2, qq = tid & 3;

    const uint4* __restrict__ Bb = g_pk + 2 * 2 * 2048;   // We[:,256:384]
    const uint4* __restrict__ Blo = Bb + 2048;
    int boff = warpn * 64 + lane;
    uint4 bh[16];
    #pragma unroll
    for (int ks = 0; ks < 8; ++ks) {
        bh[2 * ks] = __ldg(Bb + ks * 256 + boff);
        bh[2 * ks + 1] = __ldg(Bb + ks * 256 + boff + 32);
    }

    int t = blockIdx.x;
    if (t >= ntiles) return;

    float4 P[4];
    {
        const float4* gr = reinterpret_cast<const float4*>(ef + (size_t)(t * 64 + row) * D + qq * 32);
        #pragma unroll
        for (int j = 0; j < 4; ++j) P[j] = __ldcs(gr + j);
    }

    while (t < ntiles) {
        {   // fill A: prefetched half + direct (streaming) half
            const float4* gr = reinterpret_cast<const float4*>(ef + (size_t)(t * 64 + row) * D + qq * 32);
            float4 Dq[4];
            #pragma unroll
            for (int j = 0; j < 4; ++j) Dq[j] = __ldcs(gr + 4 + j);
            char* ph = smem + row * ROWB + qq * 64;
            cvt_store(ph, P[0], P[1], 0, 1.f);
            cvt_store(ph, P[2], P[3], 1, 1.f);
            cvt_store(ph, Dq[0], Dq[1], 2, 1.f);
            cvt_store(ph, Dq[2], Dq[3], 3, 1.f);
        }
        __syncthreads();
        int tn = t + gridDim.x;
        if (tn < ntiles) {
            const float4* gr = reinterpret_cast<const float4*>(ef + (size_t)(tn * 64 + row) * D + qq * 32);
            #pragma unroll
            for (int j = 0; j < 4; ++j) P[j] = __ldcs(gr + j);
        }

        float acc[2][4][4];
        ZERO_ACC(acc);
        run_mma_breg(sa, bh, Blo, boff, warpm, lane, acc);

        // stage acc -> smem (row-coalesced epilogue)
        #pragma unroll
        for (int i = 0; i < 2; ++i)
            #pragma unroll
            for (int rh = 0; rh < 2; ++rh) {
                int rl = warpm * 32 + i * 16 + rh * 8 + r4;
                #pragma unroll
                for (int nt = 0; nt < 4; ++nt) {
                    int col = warpn * 32 + nt * 8 + q * 2;
                    *reinterpret_cast<float2*>(stage + rl * STG_STRIDE + col) =
                        make_float2(acc[i][nt][rh * 2 + 0], acc[i][nt][rh * 2 + 1]);
                }
            }
        __syncthreads();

        int mbase = t * 64;
        #pragma unroll
        for (int r = 0; r < 8; ++r) {
            int rl = warp * 8 + r;
            int m = mbase + rl;
            int s = __ldg(src + m), d2 = __ldg(dst + m);
            float4 st = *reinterpret_cast<const float4*>(stage + rl * STG_STRIDE + lane * 4);
            float4 a = __ldg(reinterpret_cast<const float4*>(g_AB + (size_t)s * 256) + lane);
            float4 b = __ldg(reinterpret_cast<const float4*>(g_AB + (size_t)d2 * 256 + 128) + lane);
            float4 v = make_float4(st.x + a.x + b.x, st.y + a.y + b.y,
                                   st.z + a.z + b.z, st.w + a.w + b.w);
            __stcs(reinterpret_cast<float4*>(e_out + (size_t)m * D) + lane, v);
            float* pg = g_agg + (size_t)d2 * D + lane * 4;
            asm volatile("red.global.add.v4.f32 [%0], {%1,%2,%3,%4};"
                         :: "l"(pg), "f"(v.x), "f"(v.y), "f"(v.z), "f"(v.w) : "memory");
            if (lane == 0) atomicAdd(&g_deg[d2], 1.0f);
        }
        __syncthreads();
        t = tn;
    }
}

// k_node: persistent; two K-stages (nf, agg/deg), B via gmem (R6 style)
__global__ void __launch_bounds__(256, 2)
k_node(const float* __restrict__ nf, const float* __restrict__ b_n,
       float* __restrict__ n_out, int N) {
    extern __shared__ char smem[];
    uint32_t sa = smem_u32(smem);
    int tid = threadIdx.x, lane = tid & 31, warp = tid >> 5;
    int warpm = warp >> 2, warpn = warp & 3;
    int ntiles = (N + 63) >> 6;
    int q = lane & 3, r4 = lane >> 2;
    int row = tid >> 2, qq = tid & 3;

    for (int t = blockIdx.x; t < ntiles; t += gridDim.x) {
        int mbase = t * 64;
        int nrows = min(64, N - mbase);

        {
            bool v = row < nrows;
            const float4* gr = reinterpret_cast<const float4*>(nf + (size_t)(mbase + row) * D + qq * 32);
            char* ph = smem + row * ROWB + qq * 64;
            #pragma unroll
            for (int jj = 0; jj < 4; ++jj) {
                float4 f0 = v ? __ldg(gr + 2 * jj)     : make_float4(0.f, 0.f, 0.f, 0.f);
                float4 f1 = v ? __ldg(gr + 2 * jj + 1) : make_float4(0.f, 0.f, 0.f, 0.f);
                cvt_store(ph, f0, f1, jj, 1.f);
            }
        }
        __syncthreads();

        float acc[2][4][4];
        ZERO_ACC(acc);
        run_mma(sa, 3, warpm, warpn, lane, acc);
        __syncthreads();

        {
            bool v = row < nrows;
            float s = v ? 1.f / fmaxf(__ldg(g_deg + mbase + row), 1.f) : 1.f;
            const float4* gr = reinterpret_cast<const float4*>(g_agg + (size_t)(mbase + row) * D + qq * 32);
            char* ph = smem + row * ROWB + qq * 64;
            #pragma unroll
            for (int jj = 0; jj < 4; ++jj) {
                float4 f0 = v ? __ldg(gr + 2 * jj)     : make_float4(0.f, 0.f, 0.f, 0.f);
                float4 f1 = v ? __ldg(gr + 2 * jj + 1) : make_float4(0.f, 0.f, 0.f, 0.f);
                cvt_store(ph, f0, f1, jj, s);
            }
        }
        __syncthreads();
        run_mma(sa, 4, warpm, warpn, lane, acc);

        #pragma unroll
        for (int i = 0; i < 2; ++i)
            #pragma unroll
            for (int rh = 0; rh < 2; ++rh) {
                int m = mbase + warpm * 32 + i * 16 + rh * 8 + r4;
                if (m < N) {
                    float* pd = n_out + (size_t)m * D;
                    #pragma unroll
                    for (int nt = 0; nt < 4; ++nt) {
                        int col = warpn * 32 + nt * 8 + q * 2;
                        float2 bb = *reinterpret_cast<const float2*>(b_n + col);
                        *reinterpret_cast<float2*>(pd + col) =
                            make_float2(acc[i][nt][rh * 2 + 0] + bb.x,
                                        acc[i][nt][rh * 2 + 1] + bb.y);
                    }
                }
            }
        __syncthreads();
    }
}

// ---------------------------------------------------------------------------
extern "C" void kernel_launch(void* const* d_in, const int* in_sizes, int n_in,
                              void* d_out, int out_size) {
    const float* nf  = (const float*)d_in[0];
    const float* ef  = (const float*)d_in[1];
    const int*   src = (const int*)d_in[2];   // int32 (JAX x64 disabled)
    const int*   dst = (const int*)d_in[3];
    const float* We  = (const float*)d_in[4];
    const float* be  = (const float*)d_in[5];
    const float* Wn  = (const float*)d_in[6];
    const float* bn  = (const float*)d_in[7];

    int N = in_sizes[0] / D;
    int E = in_sizes[1] / D;

    float* n_out = (float*)d_out;
    float* e_out = n_out + (size_t)N * D;

    cudaFuncSetAttribute(k_pre,  cudaFuncAttributeMaxDynamicSharedMemorySize, SMEM_SMALL);
    cudaFuncSetAttribute(k_edge, cudaFuncAttributeMaxDynamicSharedMemorySize, SMEM_EDGE);
    cudaFuncSetAttribute(k_node, cudaFuncAttributeMaxDynamicSharedMemorySize, SMEM_SMALL);

    int zthreads = N * (D / 4);
    k_zero<<<(zthreads + 255) / 256, 256>>>(N);
    k_wprep<<<(5 * 2 * 2048 + 255) / 256, 256>>>(We, Wn);

    dim3 gpre(296, 2);
    k_pre<<<gpre, 256, SMEM_SMALL>>>(nf, be, N);
    k_edge<<<296, 256, SMEM_EDGE>>>(ef, src, dst, e_out, E);
    k_node<<<296, 256, SMEM_SMALL>>>(nf, bn, n_out, N);
}

// round 9
// speedup vs baseline: 1.6913x; 1.0637x over previous
#include <cuda_runtime.h>
#include <cuda_bf16.h>
#include <cstdint>

#define D 128
#define MAXN 40000

// ------------------------- device scratch (no allocs) -----------------------
__device__ __align__(16) float g_AB[(size_t)MAXN * 256]; // [N][256]: A=nf@W1^T | B'=nf@W2^T+b_e
__device__ __align__(16) float g_agg[(size_t)MAXN * D];
__device__ __align__(16) float g_deg[MAXN];
// Fragment-packed weights: [5 blocks][2 planes][8 ks][8 npair][32 lane] uint4
// block: 0=We[:,0:128] 1=We[:,128:256] 2=We[:,256:384] 3=Wn[:,0:128] 4=Wn[:,128:256]
__device__ __align__(16) uint4 g_pk[5 * 2 * 2048];

// ------------------------- smem layout --------------------------------------
#define ROWB 272                  // 136 bf16/row: 4-bank shift/row, LDSM conflict-free
#define A_LO_OFF 17408            // 64*272
#define SMEM_TILE 34816

__device__ __forceinline__ uint32_t smem_u32(const void* p) {
    uint32_t a;
    asm("{ .reg .u64 t; cvta.to.shared.u64 t, %1; cvt.u32.u64 %0, t; }" : "=r"(a) : "l"(p));
    return a;
}

#define LDM4(r, addr) \
    asm volatile("ldmatrix.sync.aligned.m8n8.x4.shared.b16 {%0,%1,%2,%3}, [%4];" \
        : "=r"((r)[0]), "=r"((r)[1]), "=r"((r)[2]), "=r"((r)[3]) : "r"(addr))

__device__ __forceinline__ void mma16816(float* c, const uint32_t* a, uint32_t b0, uint32_t b1) {
    asm volatile("mma.sync.aligned.m16n8k16.row.col.f32.bf16.bf16.f32 "
        "{%0,%1,%2,%3}, {%4,%5,%6,%7}, {%8,%9}, {%0,%1,%2,%3};"
        : "+f"(c[0]), "+f"(c[1]), "+f"(c[2]), "+f"(c[3])
        : "r"(a[0]), "r"(a[1]), "r"(a[2]), "r"(a[3]), "r"(b0), "r"(b1));
}

__device__ __forceinline__ void split2(float x, float y, uint32_t& h, uint32_t& l) {
    __nv_bfloat162 hh = __floats2bfloat162_rn(x, y);
    __nv_bfloat162 ll = __floats2bfloat162_rn(x - __bfloat162float(hh.x),
                                              y - __bfloat162float(hh.y));
    h = *reinterpret_cast<uint32_t*>(&hh);
    l = *reinterpret_cast<uint32_t*>(&ll);
}

__device__ __forceinline__ void cvt_store(char* ph, float4 f0, float4 f1, int jj, float s) {
    f0.x *= s; f0.y *= s; f0.z *= s; f0.w *= s;
    f1.x *= s; f1.y *= s; f1.z *= s; f1.w *= s;
    uint4 H, L;
    split2(f0.x, f0.y, H.x, L.x);
    split2(f0.z, f0.w, H.y, L.y);
    split2(f1.x, f1.y, H.z, L.z);
    split2(f1.z, f1.w, H.w, L.w);
    *reinterpret_cast<uint4*>(ph + jj * 16) = H;
    *reinterpret_cast<uint4*>(ph + A_LO_OFF + jj * 16) = L;
}

// ---- 8-mma block helper -----------------------------------------------------
__device__ __forceinline__ void mma8(float acc[2][4][4], const uint32_t* a0,
                                     const uint32_t* a1, uint4 U0, uint4 U1) {
    mma16816(acc[0][0], a0, U0.x, U0.y);
    mma16816(acc[0][1], a0, U0.z, U0.w);
    mma16816(acc[0][2], a0, U1.x, U1.y);
    mma16816(acc[0][3], a0, U1.z, U1.w);
    mma16816(acc[1][0], a1, U0.x, U0.y);
    mma16816(acc[1][1], a1, U0.z, U0.w);
    mma16816(acc[1][2], a1, U1.x, U1.y);
    mma16816(acc[1][3], a1, U1.z, U1.w);
}

// 3-pass MMA, B_hi from persistent regs, B_lo from L1, a_hi LDSM reused
__device__ __forceinline__ void run_mma_breg(uint32_t sa, const uint4* bh,
                                             const uint4* __restrict__ Blo, int boff,
                                             int warpm, int lane, float acc[2][4][4]) {
    uint32_t arow = sa + (warpm * 32 + (lane & 15)) * ROWB + (lane >> 4) * 16;
    #pragma unroll
    for (int ks = 0; ks < 8; ++ks) {
        uint32_t a0[4], a1[4], c0[4], c1[4];
        uint4 V0 = __ldg(Blo + ks * 256 + boff);
        uint4 V1 = __ldg(Blo + ks * 256 + boff + 32);
        LDM4(a0, arow + ks * 32);
        LDM4(a1, arow + 16 * ROWB + ks * 32);
        uint4 U0 = bh[2 * ks], U1 = bh[2 * ks + 1];
        mma8(acc, a0, a1, U0, U1);                       // hi x hi
        mma8(acc, a0, a1, V0, V1);                       // hi x lo
        LDM4(c0, arow + A_LO_OFF + ks * 32);
        LDM4(c1, arow + A_LO_OFF + 16 * ROWB + ks * 32);
        mma8(acc, c0, c1, U0, U1);                       // lo x hi
    }
}

// legacy 3-pass (B fully from gmem) for k_node
__device__ __forceinline__ void run_mma(uint32_t sa, int block, int warpm, int warpn,
                                        int lane, float acc[2][4][4]) {
    uint32_t arow = sa + (warpm * 32 + (lane & 15)) * ROWB + (lane >> 4) * 16;
    const uint4* __restrict__ Bb = g_pk + (size_t)block * 2 * 2048;
    int boff = warpn * 64 + lane;
    #pragma unroll
    for (int ks = 0; ks < 8; ++ks) {
        uint32_t a0[4], a1[4], c0[4], c1[4];
        uint4 U0 = __ldg(Bb + ks * 256 + boff);
        uint4 U1 = __ldg(Bb + ks * 256 + boff + 32);
        uint4 V0 = __ldg(Bb + 2048 + ks * 256 + boff);
        uint4 V1 = __ldg(Bb + 2048 + ks * 256 + boff + 32);
        LDM4(a0, arow + ks * 32);
        LDM4(a1, arow + 16 * ROWB + ks * 32);
        mma8(acc, a0, a1, U0, U1);
        mma8(acc, a0, a1, V0, V1);
        LDM4(c0, arow + A_LO_OFF + ks * 32);
        LDM4(c1, arow + A_LO_OFF + 16 * ROWB + ks * 32);
        mma8(acc, c0, c1, U0, U1);
    }
}

#define ZERO_ACC(acc) { \
    _Pragma("unroll") for (int i_ = 0; i_ < 2; ++i_) \
    _Pragma("unroll") for (int j_ = 0; j_ < 4; ++j_) \
    _Pragma("unroll") for (int k_ = 0; k_ < 4; ++k_) (acc)[i_][j_][k_] = 0.f; }

// ------------------------- tiny kernels -------------------------------------
__global__ void k_zero(int n_nodes) {
    int i = blockIdx.x * blockDim.x + threadIdx.x;
    int tot4 = n_nodes * (D / 4);
    if (i < tot4) reinterpret_cast<float4*>(g_agg)[i] = make_float4(0.f, 0.f, 0.f, 0.f);
    if (i < n_nodes) g_deg[i] = 0.f;
}

__global__ void k_wprep(const float* __restrict__ We, const float* __restrict__ Wn) {
    int idx = blockIdx.x * blockDim.x + threadIdx.x;
    if (idx >= 5 * 2 * 2048) return;
    int lane = idx & 31, npair = (idx >> 5) & 7, ks = (idx >> 8) & 7;
    int plane = (idx >> 11) & 1, b = idx >> 12;
    const float* W;
    int colbase, ldk;
    if (b < 3) { W = We; ldk = 384; colbase = b * 128; }
    else       { W = Wn; ldk = 256; colbase = (b - 3) * 128; }
    uint32_t out[4];
    #pragma unroll
    for (int j = 0; j < 4; ++j) {
        int n = (npair * 2 + (j >> 1)) * 8 + (lane >> 2);
        int k = ks * 16 + (lane & 3) * 2 + (j & 1) * 8;
        float w0 = W[(size_t)n * ldk + colbase + k];
        float w1 = W[(size_t)n * ldk + colbase + k + 1];
        __nv_bfloat16 h0 = __float2bfloat16(w0), h1 = __float2bfloat16(w1);
        __nv_bfloat162 v;
        if (plane) {
            v.x = __float2bfloat16(w0 - __bfloat162float(h0));
            v.y = __float2bfloat16(w1 - __bfloat162float(h1));
        } else { v.x = h0; v.y = h1; }
        out[j] = *reinterpret_cast<uint32_t*>(&v);
    }
    g_pk[idx] = make_uint4(out[0], out[1], out[2], out[3]);
}

// ------------------------- main kernels -------------------------------------
// k_pre: persistent, grid (G,2); Bhi regs
__global__ void __launch_bounds__(256, 2)
k_pre(const float* __restrict__ nf, const float* __restrict__ b_e, int N) {
    extern __shared__ char smem[];
    uint32_t sa = smem_u32(smem);
    int tid = threadIdx.x, lane = tid & 31, warp = tid >> 5;
    int warpm = warp >> 2, warpn = warp & 3;
    int half = blockIdx.y;
    int ntiles = (N + 63) >> 6;
    int q = lane & 3, r4 = lane >> 2;
    int row = tid >> 2, qq = tid & 3;

    const uint4* __restrict__ Bb = g_pk + (size_t)half * 2 * 2048;
    const uint4* __restrict__ Blo = Bb + 2048;
    int boff = warpn * 64 + lane;
    uint4 bh[16];
    #pragma unroll
    for (int ks = 0; ks < 8; ++ks) {
        bh[2 * ks] = __ldg(Bb + ks * 256 + boff);
        bh[2 * ks + 1] = __ldg(Bb + ks * 256 + boff + 32);
    }

    int t = blockIdx.x;
    if (t >= ntiles) return;

    float4 P[4];
    {
        bool v = t * 64 + row < N;
        const float4* gr = reinterpret_cast<const float4*>(nf + (size_t)(t * 64 + row) * D + qq * 32);
        #pragma unroll
        for (int j = 0; j < 4; ++j)
            P[j] = v ? __ldg(gr + j) : make_float4(0.f, 0.f, 0.f, 0.f);
    }

    while (t < ntiles) {
        {   // fill A: prefetched half + direct half
            bool v = t * 64 + row < N;
            const float4* gr = reinterpret_cast<const float4*>(nf + (size_t)(t * 64 + row) * D + qq * 32);
            float4 Dq[4];
            #pragma unroll
            for (int j = 0; j < 4; ++j)
                Dq[j] = v ? __ldg(gr + 4 + j) : make_float4(0.f, 0.f, 0.f, 0.f);
            char* ph = smem + row * ROWB + qq * 64;
            cvt_store(ph, P[0], P[1], 0, 1.f);
            cvt_store(ph, P[2], P[3], 1, 1.f);
            cvt_store(ph, Dq[0], Dq[1], 2, 1.f);
            cvt_store(ph, Dq[2], Dq[3], 3, 1.f);
        }
        __syncthreads();
        int tn = t + gridDim.x;
        if (tn < ntiles) {
            bool v = tn * 64 + row < N;
            const float4* gr = reinterpret_cast<const float4*>(nf + (size_t)(tn * 64 + row) * D + qq * 32);
            #pragma unroll
            for (int j = 0; j < 4; ++j)
                P[j] = v ? __ldg(gr + j) : make_float4(0.f, 0.f, 0.f, 0.f);
        }

        float acc[2][4][4];
        ZERO_ACC(acc);
        run_mma_breg(sa, bh, Blo, boff, warpm, lane, acc);

        int mbase = t * 64;
        #pragma unroll
        for (int i = 0; i < 2; ++i)
            #pragma unroll
            for (int rh = 0; rh < 2; ++rh) {
                int m = mbase + warpm * 32 + i * 16 + rh * 8 + r4;
                if (m < N) {
                    float* pd = g_AB + (size_t)m * 256 + half * 128;
                    #pragma unroll
                    for (int nt = 0; nt < 4; ++nt) {
                        int col = warpn * 32 + nt * 8 + q * 2;
                        float vx = acc[i][nt][rh * 2 + 0];
                        float vy = acc[i][nt][rh * 2 + 1];
                        if (half == 1) {
                            float2 bb = *reinterpret_cast<const float2*>(b_e + col);
                            vx += bb.x; vy += bb.y;
                        }
                        *reinterpret_cast<float2*>(pd + col) = make_float2(vx, vy);
                    }
                }
            }
        __syncthreads();
        t = tn;
    }
}

// k_edge: persistent; Bhi regs; streaming hints; scattered fragment epilogue
__global__ void __launch_bounds__(256, 2)
k_edge(const float* __restrict__ ef, const int* __restrict__ src,
       const int* __restrict__ dst, float* __restrict__ e_out, int E) {
    extern __shared__ char smem[];
    uint32_t sa = smem_u32(smem);
    int tid = threadIdx.x, lane = tid & 31, warp = tid >> 5;
    int warpm = warp >> 2, warpn = warp & 3;
    int ntiles = E >> 6;
    int q = lane & 3, r4 = lane >> 2;
    int row = tid >> 2, qq = tid & 3;

    const uint4* __restrict__ Bb = g_pk + 2 * 2 * 2048;   // We[:,256:384]
    const uint4* __restrict__ Blo = Bb + 2048;
    int boff = warpn * 64 + lane;
    uint4 bh[16];
    #pragma unroll
    for (int ks = 0; ks < 8; ++ks) {
        bh[2 * ks] = __ldg(Bb + ks * 256 + boff);
        bh[2 * ks + 1] = __ldg(Bb + ks * 256 + boff + 32);
    }

    int t = blockIdx.x;
    if (t >= ntiles) return;

    float4 P[4];
    {
        const float4* gr = reinterpret_cast<const float4*>(ef + (size_t)(t * 64 + row) * D + qq * 32);
        #pragma unroll
        for (int j = 0; j < 4; ++j) P[j] = __ldcs(gr + j);
    }

    while (t < ntiles) {
        {   // fill A: prefetched half + direct (streaming) half
            const float4* gr = reinterpret_cast<const float4*>(ef + (size_t)(t * 64 + row) * D + qq * 32);
            float4 Dq[4];
            #pragma unroll
            for (int j = 0; j < 4; ++j) Dq[j] = __ldcs(gr + 4 + j);
            char* ph = smem + row * ROWB + qq * 64;
            cvt_store(ph, P[0], P[1], 0, 1.f);
            cvt_store(ph, P[2], P[3], 1, 1.f);
            cvt_store(ph, Dq[0], Dq[1], 2, 1.f);
            cvt_store(ph, Dq[2], Dq[3], 3, 1.f);
        }
        __syncthreads();
        int tn = t + gridDim.x;
        if (tn < ntiles) {
            const float4* gr = reinterpret_cast<const float4*>(ef + (size_t)(tn * 64 + row) * D + qq * 32);
            #pragma unroll
            for (int j = 0; j < 4; ++j) P[j] = __ldcs(gr + j);
        }

        float acc[2][4][4];
        ZERO_ACC(acc);
        run_mma_breg(sa, bh, Blo, boff, warpm, lane, acc);

        // scattered fragment epilogue: per (i,rh) the 4 q-lanes cover one
        // contiguous 32B sector per row -> 8 sectors per instruction.
        int mbase = t * 64;
        #pragma unroll
        for (int i = 0; i < 2; ++i)
            #pragma unroll
            for (int rh = 0; rh < 2; ++rh) {
                int rl = warpm * 32 + i * 16 + rh * 8 + r4;
                int m = mbase + rl;
                int s = __ldg(src + m), d2 = __ldg(dst + m);
                const float* pA = g_AB + (size_t)s * 256;
                const float* pB = g_AB + (size_t)d2 * 256 + 128;
                float* pe = e_out + (size_t)m * D;
                float* pg = g_agg + (size_t)d2 * D;
                #pragma unroll
                for (int nt = 0; nt < 4; ++nt) {
                    int col = warpn * 32 + nt * 8 + q * 2;
                    float2 av = *reinterpret_cast<const float2*>(pA + col);
                    float2 bv = *reinterpret_cast<const float2*>(pB + col);
                    float vx = acc[i][nt][rh * 2 + 0] + av.x + bv.x;
                    float vy = acc[i][nt][rh * 2 + 1] + av.y + bv.y;
                    __stcs(reinterpret_cast<float2*>(pe + col), make_float2(vx, vy));
                    asm volatile("red.global.add.v2.f32 [%0], {%1,%2};"
                                 :: "l"(pg + col), "f"(vx), "f"(vy) : "memory");
                }
                if (q == 0 && warpn == 0) atomicAdd(&g_deg[d2], 1.0f);
            }
        __syncthreads();
        t = tn;
    }
}

// k_node: persistent; two K-stages (nf, agg/deg), B via gmem
__global__ void __launch_bounds__(256, 2)
k_node(const float* __restrict__ nf, const float* __restrict__ b_n,
       float* __restrict__ n_out, int N) {
    extern __shared__ char smem[];
    uint32_t sa = smem_u32(smem);
    int tid = threadIdx.x, lane = tid & 31, warp = tid >> 5;
    int warpm = warp >> 2, warpn = warp & 3;
    int ntiles = (N + 63) >> 6;
    int q = lane & 3, r4 = lane >> 2;
    int row = tid >> 2, qq = tid & 3;

    for (int t = blockIdx.x; t < ntiles; t += gridDim.x) {
        int mbase = t * 64;
        int nrows = min(64, N - mbase);

        {
            bool v = row < nrows;
            const float4* gr = reinterpret_cast<const float4*>(nf + (size_t)(mbase + row) * D + qq * 32);
            char* ph = smem + row * ROWB + qq * 64;
            #pragma unroll
            for (int jj = 0; jj < 4; ++jj) {
                float4 f0 = v ? __ldg(gr + 2 * jj)     : make_float4(0.f, 0.f, 0.f, 0.f);
                float4 f1 = v ? __ldg(gr + 2 * jj + 1) : make_float4(0.f, 0.f, 0.f, 0.f);
                cvt_store(ph, f0, f1, jj, 1.f);
            }
        }
        __syncthreads();

        float acc[2][4][4];
        ZERO_ACC(acc);
        run_mma(sa, 3, warpm, warpn, lane, acc);
        __syncthreads();

        {
            bool v = row < nrows;
            float s = v ? 1.f / fmaxf(__ldg(g_deg + mbase + row), 1.f) : 1.f;
            const float4* gr = reinterpret_cast<const float4*>(g_agg + (size_t)(mbase + row) * D + qq * 32);
            char* ph = smem + row * ROWB + qq * 64;
            #pragma unroll
            for (int jj = 0; jj < 4; ++jj) {
                float4 f0 = v ? __ldg(gr + 2 * jj)     : make_float4(0.f, 0.f, 0.f, 0.f);
                float4 f1 = v ? __ldg(gr + 2 * jj + 1) : make_float4(0.f, 0.f, 0.f, 0.f);
                cvt_store(ph, f0, f1, jj, s);
            }
        }
        __syncthreads();
        run_mma(sa, 4, warpm, warpn, lane, acc);

        #pragma unroll
        for (int i = 0; i < 2; ++i)
            #pragma unroll
            for (int rh = 0; rh < 2; ++rh) {
                int m = mbase + warpm * 32 + i * 16 + rh * 8 + r4;
                if (m < N) {
                    float* pd = n_out + (size_t)m * D;
                    #pragma unroll
                    for (int nt = 0; nt < 4; ++nt) {
                        int col = warpn * 32 + nt * 8 + q * 2;
                        float2 bb = *reinterpret_cast<const float2*>(b_n + col);
                        *reinterpret_cast<float2*>(pd + col) =
                            make_float2(acc[i][nt][rh * 2 + 0] + bb.x,
                                        acc[i][nt][rh * 2 + 1] + bb.y);
                    }
                }
            }
        __syncthreads();
    }
}

// ---------------------------------------------------------------------------
extern "C" void kernel_launch(void* const* d_in, const int* in_sizes, int n_in,
                              void* d_out, int out_size) {
    const float* nf  = (const float*)d_in[0];
    const float* ef  = (const float*)d_in[1];
    const int*   src = (const int*)d_in[2];   // int32 (JAX x64 disabled)
    const int*   dst = (const int*)d_in[3];
    const float* We  = (const float*)d_in[4];
    const float* be  = (const float*)d_in[5];
    const float* Wn  = (const float*)d_in[6];
    const float* bn  = (const float*)d_in[7];

    int N = in_sizes[0] / D;
    int E = in_sizes[1] / D;

    float* n_out = (float*)d_out;
    float* e_out = n_out + (size_t)N * D;

    cudaFuncSetAttribute(k_pre,  cudaFuncAttributeMaxDynamicSharedMemorySize, SMEM_TILE);
    cudaFuncSetAttribute(k_edge, cudaFuncAttributeMaxDynamicSharedMemorySize, SMEM_TILE);
    cudaFuncSetAttribute(k_node, cudaFuncAttributeMaxDynamicSharedMemorySize, SMEM_TILE);

    int zthreads = N * (D / 4);
    k_zero<<<(zthreads + 255) / 256, 256>>>(N);
    k_wprep<<<(5 * 2 * 2048 + 255) / 256, 256>>>(We, Wn);

    dim3 gpre(296, 2);
    k_pre<<<gpre, 256, SMEM_TILE>>>(nf, be, N);
    k_edge<<<296, 256, SMEM_TILE>>>(ef, src, dst, e_out, E);
    k_node<<<296, 256, SMEM_TILE>>>(nf, bn, n_out, N);
}

// round 10
// speedup vs baseline: 1.8975x; 1.1219x over previous
#include <cuda_runtime.h>
#include <cuda_bf16.h>
#include <cstdint>

#define D 128
#define MAXN 40000

// ------------------------- device scratch (no allocs) -----------------------
__device__ __align__(16) float g_AB[(size_t)MAXN * 256]; // [N][256]: A=nf@W1^T | B'=nf@W2^T+b_e
__device__ __align__(16) float g_agg[(size_t)MAXN * D];
__device__ __align__(16) float g_deg[MAXN];
// Fragment-packed weights: [5 blocks][2 planes][8 ks][8 npair][32 lane] uint4
// block: 0=We[:,0:128] 1=We[:,128:256] 2=We[:,256:384] 3=Wn[:,0:128] 4=Wn[:,128:256]
__device__ __align__(16) uint4 g_pk[5 * 2 * 2048];

// ------------------------- smem layout --------------------------------------
#define ROWB 272                  // 136 bf16/row: 4-bank shift/row, LDSM conflict-free
#define A_LO_OFF 17408            // 64*272
#define SMEM_TILE 34816

__device__ __forceinline__ uint32_t smem_u32(const void* p) {
    uint32_t a;
    asm("{ .reg .u64 t; cvta.to.shared.u64 t, %1; cvt.u32.u64 %0, t; }" : "=r"(a) : "l"(p));
    return a;
}

#define LDM4(r, addr) \
    asm volatile("ldmatrix.sync.aligned.m8n8.x4.shared.b16 {%0,%1,%2,%3}, [%4];" \
        : "=r"((r)[0]), "=r"((r)[1]), "=r"((r)[2]), "=r"((r)[3]) : "r"(addr))

__device__ __forceinline__ void mma16816(float* c, const uint32_t* a, uint32_t b0, uint32_t b1) {
    asm volatile("mma.sync.aligned.m16n8k16.row.col.f32.bf16.bf16.f32 "
        "{%0,%1,%2,%3}, {%4,%5,%6,%7}, {%8,%9}, {%0,%1,%2,%3};"
        : "+f"(c[0]), "+f"(c[1]), "+f"(c[2]), "+f"(c[3])
        : "r"(a[0]), "r"(a[1]), "r"(a[2]), "r"(a[3]), "r"(b0), "r"(b1));
}

// NOTE: no "memory" clobber — g_agg is never read in this kernel, and removing
// the clobber lets the compiler hoist independent gather loads above the red,
// turning the epilogue from 16 serial L2 round-trips into a batched issue.
__device__ __forceinline__ void red_v2(float* p, float x, float y) {
    asm volatile("red.global.add.v2.f32 [%0], {%1,%2};" :: "l"(p), "f"(x), "f"(y));
}

__device__ __forceinline__ float2 ldcg2(const float* p) {
    float2 v;
    asm volatile("ld.global.cg.v2.f32 {%0,%1}, [%2];" : "=f"(v.x), "=f"(v.y) : "l"(p));
    return v;
}

__device__ __forceinline__ void split2(float x, float y, uint32_t& h, uint32_t& l) {
    __nv_bfloat162 hh = __floats2bfloat162_rn(x, y);
    __nv_bfloat162 ll = __floats2bfloat162_rn(x - __bfloat162float(hh.x),
                                              y - __bfloat162float(hh.y));
    h = *reinterpret_cast<uint32_t*>(&hh);
    l = *reinterpret_cast<uint32_t*>(&ll);
}

__device__ __forceinline__ void cvt_store(char* ph, float4 f0, float4 f1, int jj, float s) {
    f0.x *= s; f0.y *= s; f0.z *= s; f0.w *= s;
    f1.x *= s; f1.y *= s; f1.z *= s; f1.w *= s;
    uint4 H, L;
    split2(f0.x, f0.y, H.x, L.x);
    split2(f0.z, f0.w, H.y, L.y);
    split2(f1.x, f1.y, H.z, L.z);
    split2(f1.z, f1.w, H.w, L.w);
    *reinterpret_cast<uint4*>(ph + jj * 16) = H;
    *reinterpret_cast<uint4*>(ph + A_LO_OFF + jj * 16) = L;
}

// ---- 8-mma block helper -----------------------------------------------------
__device__ __forceinline__ void mma8(float acc[2][4][4], const uint32_t* a0,
                                     const uint32_t* a1, uint4 U0, uint4 U1) {
    mma16816(acc[0][0], a0, U0.x, U0.y);
    mma16816(acc[0][1], a0, U0.z, U0.w);
    mma16816(acc[0][2], a0, U1.x, U1.y);
    mma16816(acc[0][3], a0, U1.z, U1.w);
    mma16816(acc[1][0], a1, U0.x, U0.y);
    mma16816(acc[1][1], a1, U0.z, U0.w);
    mma16816(acc[1][2], a1, U1.x, U1.y);
    mma16816(acc[1][3], a1, U1.z, U1.w);
}

// 3-pass MMA, B_hi from persistent regs, B_lo from L1, a_hi LDSM reused
__device__ __forceinline__ void run_mma_breg(uint32_t sa, const uint4* bh,
                                             const uint4* __restrict__ Blo, int boff,
                                             int warpm, int lane, float acc[2][4][4]) {
    uint32_t arow = sa + (warpm * 32 + (lane & 15)) * ROWB + (lane >> 4) * 16;
    #pragma unroll
    for (int ks = 0; ks < 8; ++ks) {
        uint32_t a0[4], a1[4], c0[4], c1[4];
        uint4 V0 = __ldg(Blo + ks * 256 + boff);
        uint4 V1 = __ldg(Blo + ks * 256 + boff + 32);
        LDM4(a0, arow + ks * 32);
        LDM4(a1, arow + 16 * ROWB + ks * 32);
        uint4 U0 = bh[2 * ks], U1 = bh[2 * ks + 1];
        mma8(acc, a0, a1, U0, U1);                       // hi x hi
        mma8(acc, a0, a1, V0, V1);                       // hi x lo
        LDM4(c0, arow + A_LO_OFF + ks * 32);
        LDM4(c1, arow + A_LO_OFF + 16 * ROWB + ks * 32);
        mma8(acc, c0, c1, U0, U1);                       // lo x hi
    }
}

// legacy 3-pass (B fully from gmem) for k_node
__device__ __forceinline__ void run_mma(uint32_t sa, int block, int warpm, int warpn,
                                        int lane, float acc[2][4][4]) {
    uint32_t arow = sa + (warpm * 32 + (lane & 15)) * ROWB + (lane >> 4) * 16;
    const uint4* __restrict__ Bb = g_pk + (size_t)block * 2 * 2048;
    int boff = warpn * 64 + lane;
    #pragma unroll
    for (int ks = 0; ks < 8; ++ks) {
        uint32_t a0[4], a1[4], c0[4], c1[4];
        uint4 U0 = __ldg(Bb + ks * 256 + boff);
        uint4 U1 = __ldg(Bb + ks * 256 + boff + 32);
        uint4 V0 = __ldg(Bb + 2048 + ks * 256 + boff);
        uint4 V1 = __ldg(Bb + 2048 + ks * 256 + boff + 32);
        LDM4(a0, arow + ks * 32);
        LDM4(a1, arow + 16 * ROWB + ks * 32);
        mma8(acc, a0, a1, U0, U1);
        mma8(acc, a0, a1, V0, V1);
        LDM4(c0, arow + A_LO_OFF + ks * 32);
        LDM4(c1, arow + A_LO_OFF + 16 * ROWB + ks * 32);
        mma8(acc, c0, c1, U0, U1);
    }
}

#define ZERO_ACC(acc) { \
    _Pragma("unroll") for (int i_ = 0; i_ < 2; ++i_) \
    _Pragma("unroll") for (int j_ = 0; j_ < 4; ++j_) \
    _Pragma("unroll") for (int k_ = 0; k_ < 4; ++k_) (acc)[i_][j_][k_] = 0.f; }

// ------------------------- tiny kernels -------------------------------------
__global__ void k_zero(int n_nodes) {
    int i = blockIdx.x * blockDim.x + threadIdx.x;
    int tot4 = n_nodes * (D / 4);
    if (i < tot4) reinterpret_cast<float4*>(g_agg)[i] = make_float4(0.f, 0.f, 0.f, 0.f);
    if (i < n_nodes) g_deg[i] = 0.f;
}

__global__ void k_wprep(const float* __restrict__ We, const float* __restrict__ Wn) {
    int idx = blockIdx.x * blockDim.x + threadIdx.x;
    if (idx >= 5 * 2 * 2048) return;
    int lane = idx & 31, npair = (idx >> 5) & 7, ks = (idx >> 8) & 7;
    int plane = (idx >> 11) & 1, b = idx >> 12;
    const float* W;
    int colbase, ldk;
    if (b < 3) { W = We; ldk = 384; colbase = b * 128; }
    else       { W = Wn; ldk = 256; colbase = (b - 3) * 128; }
    uint32_t out[4];
    #pragma unroll
    for (int j = 0; j < 4; ++j) {
        int n = (npair * 2 + (j >> 1)) * 8 + (lane >> 2);
        int k = ks * 16 + (lane & 3) * 2 + (j & 1) * 8;
        float w0 = W[(size_t)n * ldk + colbase + k];
        float w1 = W[(size_t)n * ldk + colbase + k + 1];
        __nv_bfloat16 h0 = __float2bfloat16(w0), h1 = __float2bfloat16(w1);
        __nv_bfloat162 v;
        if (plane) {
            v.x = __float2bfloat16(w0 - __bfloat162float(h0));
            v.y = __float2bfloat16(w1 - __bfloat162float(h1));
        } else { v.x = h0; v.y = h1; }
        out[j] = *reinterpret_cast<uint32_t*>(&v);
    }
    g_pk[idx] = make_uint4(out[0], out[1], out[2], out[3]);
}

// ------------------------- main kernels -------------------------------------
// k_pre: persistent, grid (G,2); Bhi regs
__global__ void __launch_bounds__(256, 2)
k_pre(const float* __restrict__ nf, const float* __restrict__ b_e, int N) {
    extern __shared__ char smem[];
    uint32_t sa = smem_u32(smem);
    int tid = threadIdx.x, lane = tid & 31, warp = tid >> 5;
    int warpm = warp >> 2, warpn = warp & 3;
    int half = blockIdx.y;
    int ntiles = (N + 63) >> 6;
    int q = lane & 3, r4 = lane >> 2;
    int row = tid >> 2, qq = tid & 3;

    const uint4* __restrict__ Bb = g_pk + (size_t)half * 2 * 2048;
    const uint4* __restrict__ Blo = Bb + 2048;
    int boff = warpn * 64 + lane;
    uint4 bh[16];
    #pragma unroll
    for (int ks = 0; ks < 8; ++ks) {
        bh[2 * ks] = __ldg(Bb + ks * 256 + boff);
        bh[2 * ks + 1] = __ldg(Bb + ks * 256 + boff + 32);
    }

    int t = blockIdx.x;
    if (t >= ntiles) return;

    float4 P[4];
    {
        bool v = t * 64 + row < N;
        const float4* gr = reinterpret_cast<const float4*>(nf + (size_t)(t * 64 + row) * D + qq * 32);
        #pragma unroll
        for (int j = 0; j < 4; ++j)
            P[j] = v ? __ldg(gr + j) : make_float4(0.f, 0.f, 0.f, 0.f);
    }

    while (t < ntiles) {
        {   // fill A: prefetched half + direct half
            bool v = t * 64 + row < N;
            const float4* gr = reinterpret_cast<const float4*>(nf + (size_t)(t * 64 + row) * D + qq * 32);
            float4 Dq[4];
            #pragma unroll
            for (int j = 0; j < 4; ++j)
                Dq[j] = v ? __ldg(gr + 4 + j) : make_float4(0.f, 0.f, 0.f, 0.f);
            char* ph = smem + row * ROWB + qq * 64;
            cvt_store(ph, P[0], P[1], 0, 1.f);
            cvt_store(ph, P[2], P[3], 1, 1.f);
            cvt_store(ph, Dq[0], Dq[1], 2, 1.f);
            cvt_store(ph, Dq[2], Dq[3], 3, 1.f);
        }
        __syncthreads();
        int tn = t + gridDim.x;
        if (tn < ntiles) {
            bool v = tn * 64 + row < N;
            const float4* gr = reinterpret_cast<const float4*>(nf + (size_t)(tn * 64 + row) * D + qq * 32);
            #pragma unroll
            for (int j = 0; j < 4; ++j)
                P[j] = v ? __ldg(gr + j) : make_float4(0.f, 0.f, 0.f, 0.f);
        }

        float acc[2][4][4];
        ZERO_ACC(acc);
        run_mma_breg(sa, bh, Blo, boff, warpm, lane, acc);

        int mbase = t * 64;
        #pragma unroll
        for (int i = 0; i < 2; ++i)
            #pragma unroll
            for (int rh = 0; rh < 2; ++rh) {
                int m = mbase + warpm * 32 + i * 16 + rh * 8 + r4;
                if (m < N) {
                    float* pd = g_AB + (size_t)m * 256 + half * 128;
                    #pragma unroll
                    for (int nt = 0; nt < 4; ++nt) {
                        int col = warpn * 32 + nt * 8 + q * 2;
                        float vx = acc[i][nt][rh * 2 + 0];
                        float vy = acc[i][nt][rh * 2 + 1];
                        if (half == 1) {
                            float2 bb = *reinterpret_cast<const float2*>(b_e + col);
                            vx += bb.x; vy += bb.y;
                        }
                        *reinterpret_cast<float2*>(pd + col) = make_float2(vx, vy);
                    }
                }
            }
        __syncthreads();
        t = tn;
    }
}

// k_edge: persistent; Bhi regs; idx preloaded + deg red before MMA;
// epilogue gathers via ld.cg with no asm memory clobbers -> batched issue.
__global__ void __launch_bounds__(256, 2)
k_edge(const float* __restrict__ ef, const int* __restrict__ src,
       const int* __restrict__ dst, float* __restrict__ e_out, int E) {
    extern __shared__ char smem[];
    uint32_t sa = smem_u32(smem);
    int tid = threadIdx.x, lane = tid & 31, warp = tid >> 5;
    int warpm = warp >> 2, warpn = warp & 3;
    int ntiles = E >> 6;
    int q = lane & 3, r4 = lane >> 2;
    int row = tid >> 2, qq = tid & 3;

    const uint4* __restrict__ Bb = g_pk + 2 * 2 * 2048;   // We[:,256:384]
    const uint4* __restrict__ Blo = Bb + 2048;
    int boff = warpn * 64 + lane;
    uint4 bh[16];
    #pragma unroll
    for (int ks = 0; ks < 8; ++ks) {
        bh[2 * ks] = __ldg(Bb + ks * 256 + boff);
        bh[2 * ks + 1] = __ldg(Bb + ks * 256 + boff + 32);
    }

    int t = blockIdx.x;
    if (t >= ntiles) return;

    float4 P[4];
    {
        const float4* gr = reinterpret_cast<const float4*>(ef + (size_t)(t * 64 + row) * D + qq * 32);
        #pragma unroll
        for (int j = 0; j < 4; ++j) P[j] = __ldcs(gr + j);
    }

    while (t < ntiles) {
        {   // fill A: prefetched half + direct (streaming) half
            const float4* gr = reinterpret_cast<const float4*>(ef + (size_t)(t * 64 + row) * D + qq * 32);
            float4 Dq[4];
            #pragma unroll
            for (int j = 0; j < 4; ++j) Dq[j] = __ldcs(gr + 4 + j);
            char* ph = smem + row * ROWB + qq * 64;
            cvt_store(ph, P[0], P[1], 0, 1.f);
            cvt_store(ph, P[2], P[3], 1, 1.f);
            cvt_store(ph, Dq[0], Dq[1], 2, 1.f);
            cvt_store(ph, Dq[2], Dq[3], 3, 1.f);
        }
        __syncthreads();
        int tn = t + gridDim.x;
        if (tn < ntiles) {
            const float4* gr = reinterpret_cast<const float4*>(ef + (size_t)(tn * 64 + row) * D + qq * 32);
            #pragma unroll
            for (int j = 0; j < 4; ++j) P[j] = __ldcs(gr + j);
        }

        // preload this tile's indices + do deg reduction now (acc-independent;
        // latency hides under the MMA below)
        int mbase = t * 64;
        int sidx[2][2], didx[2][2];
        #pragma unroll
        for (int i = 0; i < 2; ++i)
            #pragma unroll
            for (int rh = 0; rh < 2; ++rh) {
                int m = mbase + warpm * 32 + i * 16 + rh * 8 + r4;
                sidx[i][rh] = __ldg(src + m);
                didx[i][rh] = __ldg(dst + m);
                if (q == 0 && warpn == 0) atomicAdd(&g_deg[didx[i][rh]], 1.0f);
            }

        float acc[2][4][4];
        ZERO_ACC(acc);
        run_mma_breg(sa, bh, Blo, boff, warpm, lane, acc);

        #pragma unroll
        for (int i = 0; i < 2; ++i)
            #pragma unroll
            for (int rh = 0; rh < 2; ++rh) {
                int rl = warpm * 32 + i * 16 + rh * 8 + r4;
                int m = mbase + rl;
                const float* pA = g_AB + (size_t)sidx[i][rh] * 256;
                const float* pB = g_AB + (size_t)didx[i][rh] * 256 + 128;
                float* pe = e_out + (size_t)m * D;
                float* pg = g_agg + (size_t)didx[i][rh] * D;
                #pragma unroll
                for (int nt = 0; nt < 4; ++nt) {
                    int col = warpn * 32 + nt * 8 + q * 2;
                    float2 av = ldcg2(pA + col);
                    float2 bv = ldcg2(pB + col);
                    float vx = acc[i][nt][rh * 2 + 0] + av.x + bv.x;
                    float vy = acc[i][nt][rh * 2 + 1] + av.y + bv.y;
                    __stcs(reinterpret_cast<float2*>(pe + col), make_float2(vx, vy));
                    red_v2(pg + col, vx, vy);
                }
            }
        __syncthreads();
        t = tn;
    }
}

// k_node: persistent; two K-stages (nf, agg/deg), B via gmem
__global__ void __launch_bounds__(256, 2)
k_node(const float* __restrict__ nf, const float* __restrict__ b_n,
       float* __restrict__ n_out, int N) {
    extern __shared__ char smem[];
    uint32_t sa = smem_u32(smem);
    int tid = threadIdx.x, lane = tid & 31, warp = tid >> 5;
    int warpm = warp >> 2, warpn = warp & 3;
    int ntiles = (N + 63) >> 6;
    int q = lane & 3, r4 = lane >> 2;
    int row = tid >> 2, qq = tid & 3;

    for (int t = blockIdx.x; t < ntiles; t += gridDim.x) {
        int mbase = t * 64;
        int nrows = min(64, N - mbase);

        {
            bool v = row < nrows;
            const float4* gr = reinterpret_cast<const float4*>(nf + (size_t)(mbase + row) * D + qq * 32);
            char* ph = smem + row * ROWB + qq * 64;
            #pragma unroll
            for (int jj = 0; jj < 4; ++jj) {
                float4 f0 = v ? __ldg(gr + 2 * jj)     : make_float4(0.f, 0.f, 0.f, 0.f);
                float4 f1 = v ? __ldg(gr + 2 * jj + 1) : make_float4(0.f, 0.f, 0.f, 0.f);
                cvt_store(ph, f0, f1, jj, 1.f);
            }
        }
        __syncthreads();

        float acc[2][4][4];
        ZERO_ACC(acc);
        run_mma(sa, 3, warpm, warpn, lane, acc);
        __syncthreads();

        {
            bool v = row < nrows;
            float s = v ? 1.f / fmaxf(__ldg(g_deg + mbase + row), 1.f) : 1.f;
            const float4* gr = reinterpret_cast<const float4*>(g_agg + (size_t)(mbase + row) * D + qq * 32);
            char* ph = smem + row * ROWB + qq * 64;
            #pragma unroll
            for (int jj = 0; jj < 4; ++jj) {
                float4 f0 = v ? __ldg(gr + 2 * jj)     : make_float4(0.f, 0.f, 0.f, 0.f);
                float4 f1 = v ? __ldg(gr + 2 * jj + 1) : make_float4(0.f, 0.f, 0.f, 0.f);
                cvt_store(ph, f0, f1, jj, s);
            }
        }
        __syncthreads();
        run_mma(sa, 4, warpm, warpn, lane, acc);

        #pragma unroll
        for (int i = 0; i < 2; ++i)
            #pragma unroll
            for (int rh = 0; rh < 2; ++rh) {
                int m = mbase + warpm * 32 + i * 16 + rh * 8 + r4;
                if (m < N) {
                    float* pd = n_out + (size_t)m * D;
                    #pragma unroll
                    for (int nt = 0; nt < 4; ++nt) {
                        int col = warpn * 32 + nt * 8 + q * 2;
                        float2 bb = *reinterpret_cast<const float2*>(b_n + col);
                        *reinterpret_cast<float2*>(pd + col) =
                            make_float2(acc[i][nt][rh * 2 + 0] + bb.x,
                                        acc[i][nt][rh * 2 + 1] + bb.y);
                    }
                }
            }
        __syncthreads();
    }
}

// ---------------------------------------------------------------------------
extern "C" void kernel_launch(void* const* d_in, const int* in_sizes, int n_in,
                              void* d_out, int out_size) {
    const float* nf  = (const float*)d_in[0];
    const float* ef  = (const float*)d_in[1];
    const int*   src = (const int*)d_in[2];   // int32 (JAX x64 disabled)
    const int*   dst = (const int*)d_in[3];
    const float* We  = (const float*)d_in[4];
    const float* be  = (const float*)d_in[5];
    const float* Wn  = (const float*)d_in[6];
    const float* bn  = (const float*)d_in[7];

    int N = in_sizes[0] / D;
    int E = in_sizes[1] / D;

    float* n_out = (float*)d_out;
    float* e_out = n_out + (size_t)N * D;

    cudaFuncSetAttribute(k_pre,  cudaFuncAttributeMaxDynamicSharedMemorySize, SMEM_TILE);
    cudaFuncSetAttribute(k_edge, cudaFuncAttributeMaxDynamicSharedMemorySize, SMEM_TILE);
    cudaFuncSetAttribute(k_node, cudaFuncAttributeMaxDynamicSharedMemorySize, SMEM_TILE);

    int zthreads = N * (D / 4);
    k_zero<<<(zthreads + 255) / 256, 256>>>(N);
    k_wprep<<<(5 * 2 * 2048 + 255) / 256, 256>>>(We, Wn);

    dim3 gpre(296, 2);
    k_pre<<<gpre, 256, SMEM_TILE>>>(nf, be, N);
    k_edge<<<296, 256, SMEM_TILE>>>(ef, src, dst, e_out, E);
    k_node<<<296, 256, SMEM_TILE>>>(nf, bn, n_out, N);
}

// round 11
// speedup vs baseline: 2.0487x; 1.0797x over previous
#include <cuda_runtime.h>
#include <cuda_bf16.h>
#include <cstdint>

#define D 128
#define MAXN 40000

// ------------------------- device scratch (no allocs) -----------------------
__device__ __align__(16) float g_AB[(size_t)MAXN * 256]; // [N][256]: A=nf@W1^T | B'=nf@W2^T+b_e
__device__ __align__(16) float g_agg[(size_t)MAXN * D];
__device__ __align__(16) float g_deg[MAXN];
// Fragment-packed weights: [5 blocks][2 planes][8 ks][8 npair][32 lane] uint4
// block: 0=We[:,0:128] 1=We[:,128:256] 2=We[:,256:384] 3=Wn[:,0:128] 4=Wn[:,128:256]
__device__ __align__(16) uint4 g_pk[5 * 2 * 2048];

// ------------------------- smem layout --------------------------------------
#define ROWB 272                  // 136 bf16/row: 4-bank shift/row, LDSM conflict-free
#define A_LO_OFF 17408            // 64*272
#define SMEM_TILE 34816

__device__ __forceinline__ uint32_t smem_u32(const void* p) {
    uint32_t a;
    asm("{ .reg .u64 t; cvta.to.shared.u64 t, %1; cvt.u32.u64 %0, t; }" : "=r"(a) : "l"(p));
    return a;
}

#define LDM4(r, addr) \
    asm volatile("ldmatrix.sync.aligned.m8n8.x4.shared.b16 {%0,%1,%2,%3}, [%4];" \
        : "=r"((r)[0]), "=r"((r)[1]), "=r"((r)[2]), "=r"((r)[3]) : "r"(addr))

__device__ __forceinline__ void mma16816(float* c, const uint32_t* a, uint32_t b0, uint32_t b1) {
    asm volatile("mma.sync.aligned.m16n8k16.row.col.f32.bf16.bf16.f32 "
        "{%0,%1,%2,%3}, {%4,%5,%6,%7}, {%8,%9}, {%0,%1,%2,%3};"
        : "+f"(c[0]), "+f"(c[1]), "+f"(c[2]), "+f"(c[3])
        : "r"(a[0]), "r"(a[1]), "r"(a[2]), "r"(a[3]), "r"(b0), "r"(b1));
}

// no "memory" clobber: lets the compiler batch independent gathers around reds
__device__ __forceinline__ void red_v2(float* p, float x, float y) {
    asm volatile("red.global.add.v2.f32 [%0], {%1,%2};" :: "l"(p), "f"(x), "f"(y));
}

__device__ __forceinline__ float2 ldcg2(const float* p) {
    float2 v;
    asm volatile("ld.global.cg.v2.f32 {%0,%1}, [%2];" : "=f"(v.x), "=f"(v.y) : "l"(p));
    return v;
}

__device__ __forceinline__ void split2(float x, float y, uint32_t& h, uint32_t& l) {
    __nv_bfloat162 hh = __floats2bfloat162_rn(x, y);
    __nv_bfloat162 ll = __floats2bfloat162_rn(x - __bfloat162float(hh.x),
                                              y - __bfloat162float(hh.y));
    h = *reinterpret_cast<uint32_t*>(&hh);
    l = *reinterpret_cast<uint32_t*>(&ll);
}

__device__ __forceinline__ void cvt_store(char* ph, float4 f0, float4 f1, int jj, float s) {
    f0.x *= s; f0.y *= s; f0.z *= s; f0.w *= s;
    f1.x *= s; f1.y *= s; f1.z *= s; f1.w *= s;
    uint4 H, L;
    split2(f0.x, f0.y, H.x, L.x);
    split2(f0.z, f0.w, H.y, L.y);
    split2(f1.x, f1.y, H.z, L.z);
    split2(f1.z, f1.w, H.w, L.w);
    *reinterpret_cast<uint4*>(ph + jj * 16) = H;
    *reinterpret_cast<uint4*>(ph + A_LO_OFF + jj * 16) = L;
}

// ---- 8-mma block helper -----------------------------------------------------
__device__ __forceinline__ void mma8(float acc[2][4][4], const uint32_t* a0,
                                     const uint32_t* a1, uint4 U0, uint4 U1) {
    mma16816(acc[0][0], a0, U0.x, U0.y);
    mma16816(acc[0][1], a0, U0.z, U0.w);
    mma16816(acc[0][2], a0, U1.x, U1.y);
    mma16816(acc[0][3], a0, U1.z, U1.w);
    mma16816(acc[1][0], a1, U0.x, U0.y);
    mma16816(acc[1][1], a1, U0.z, U0.w);
    mma16816(acc[1][2], a1, U1.x, U1.y);
    mma16816(acc[1][3], a1, U1.z, U1.w);
}

// 3-pass 64x128x128 MMA; B hi+lo via __ldg (L1), A via LDSM, a_hi reused
__device__ __forceinline__ void run_mma(uint32_t sa, int block, int warpm, int warpn,
                                        int lane, float acc[2][4][4]) {
    uint32_t arow = sa + (warpm * 32 + (lane & 15)) * ROWB + (lane >> 4) * 16;
    const uint4* __restrict__ Bb = g_pk + (size_t)block * 2 * 2048;
    int boff = warpn * 64 + lane;
    #pragma unroll
    for (int ks = 0; ks < 8; ++ks) {
        uint32_t a0[4], a1[4], c0[4], c1[4];
        uint4 U0 = __ldg(Bb + ks * 256 + boff);
        uint4 U1 = __ldg(Bb + ks * 256 + boff + 32);
        uint4 V0 = __ldg(Bb + 2048 + ks * 256 + boff);
        uint4 V1 = __ldg(Bb + 2048 + ks * 256 + boff + 32);
        LDM4(a0, arow + ks * 32);
        LDM4(a1, arow + 16 * ROWB + ks * 32);
        mma8(acc, a0, a1, U0, U1);                       // hi x hi
        mma8(acc, a0, a1, V0, V1);                       // hi x lo
        LDM4(c0, arow + A_LO_OFF + ks * 32);
        LDM4(c1, arow + A_LO_OFF + 16 * ROWB + ks * 32);
        mma8(acc, c0, c1, U0, U1);                       // lo x hi
    }
}

#define ZERO_ACC(acc) { \
    _Pragma("unroll") for (int i_ = 0; i_ < 2; ++i_) \
    _Pragma("unroll") for (int j_ = 0; j_ < 4; ++j_) \
    _Pragma("unroll") for (int k_ = 0; k_ < 4; ++k_) (acc)[i_][j_][k_] = 0.f; }

// ------------------------- tiny kernels -------------------------------------
__global__ void k_zero(int n_nodes) {
    int i = blockIdx.x * blockDim.x + threadIdx.x;
    int tot4 = n_nodes * (D / 4);
    if (i < tot4) reinterpret_cast<float4*>(g_agg)[i] = make_float4(0.f, 0.f, 0.f, 0.f);
    if (i < n_nodes) g_deg[i] = 0.f;
}

__global__ void k_wprep(const float* __restrict__ We, const float* __restrict__ Wn) {
    int idx = blockIdx.x * blockDim.x + threadIdx.x;
    if (idx >= 5 * 2 * 2048) return;
    int lane = idx & 31, npair = (idx >> 5) & 7, ks = (idx >> 8) & 7;
    int plane = (idx >> 11) & 1, b = idx >> 12;
    const float* W;
    int colbase, ldk;
    if (b < 3) { W = We; ldk = 384; colbase = b * 128; }
    else       { W = Wn; ldk = 256; colbase = (b - 3) * 128; }
    uint32_t out[4];
    #pragma unroll
    for (int j = 0; j < 4; ++j) {
        int n = (npair * 2 + (j >> 1)) * 8 + (lane >> 2);
        int k = ks * 16 + (lane & 3) * 2 + (j & 1) * 8;
        float w0 = W[(size_t)n * ldk + colbase + k];
        float w1 = W[(size_t)n * ldk + colbase + k + 1];
        __nv_bfloat16 h0 = __float2bfloat16(w0), h1 = __float2bfloat16(w1);
        __nv_bfloat162 v;
        if (plane) {
            v.x = __float2bfloat16(w0 - __bfloat162float(h0));
            v.y = __float2bfloat16(w1 - __bfloat162float(h1));
        } else { v.x = h0; v.y = h1; }
        out[j] = *reinterpret_cast<uint32_t*>(&v);
    }
    g_pk[idx] = make_uint4(out[0], out[1], out[2], out[3]);
}

// ------------------------- main kernels -------------------------------------
// k_pre: persistent, grid (G,2)
__global__ void __launch_bounds__(256, 3)
k_pre(const float* __restrict__ nf, const float* __restrict__ b_e, int N) {
    extern __shared__ char smem[];
    uint32_t sa = smem_u32(smem);
    int tid = threadIdx.x, lane = tid & 31, warp = tid >> 5;
    int warpm = warp >> 2, warpn = warp & 3;
    int half = blockIdx.y;
    int ntiles = (N + 63) >> 6;
    int q = lane & 3, r4 = lane >> 2;
    int row = tid >> 2, qq = tid & 3;

    int t = blockIdx.x;
    if (t >= ntiles) return;

    float4 P[4];
    {
        bool v = t * 64 + row < N;
        const float4* gr = reinterpret_cast<const float4*>(nf + (size_t)(t * 64 + row) * D + qq * 32);
        #pragma unroll
        for (int j = 0; j < 4; ++j)
            P[j] = v ? __ldg(gr + j) : make_float4(0.f, 0.f, 0.f, 0.f);
    }

    while (t < ntiles) {
        {   // fill A: prefetched half + direct half
            bool v = t * 64 + row < N;
            const float4* gr = reinterpret_cast<const float4*>(nf + (size_t)(t * 64 + row) * D + qq * 32);
            float4 Dq[4];
            #pragma unroll
            for (int j = 0; j < 4; ++j)
                Dq[j] = v ? __ldg(gr + 4 + j) : make_float4(0.f, 0.f, 0.f, 0.f);
            char* ph = smem + row * ROWB + qq * 64;
            cvt_store(ph, P[0], P[1], 0, 1.f);
            cvt_store(ph, P[2], P[3], 1, 1.f);
            cvt_store(ph, Dq[0], Dq[1], 2, 1.f);
            cvt_store(ph, Dq[2], Dq[3], 3, 1.f);
        }
        __syncthreads();
        int tn = t + gridDim.x;
        if (tn < ntiles) {
            bool v = tn * 64 + row < N;
            const float4* gr = reinterpret_cast<const float4*>(nf + (size_t)(tn * 64 + row) * D + qq * 32);
            #pragma unroll
            for (int j = 0; j < 4; ++j)
                P[j] = v ? __ldg(gr + j) : make_float4(0.f, 0.f, 0.f, 0.f);
        }

        float acc[2][4][4];
        ZERO_ACC(acc);
        run_mma(sa, half, warpm, warpn, lane, acc);

        int mbase = t * 64;
        #pragma unroll
        for (int i = 0; i < 2; ++i)
            #pragma unroll
            for (int rh = 0; rh < 2; ++rh) {
                int m = mbase + warpm * 32 + i * 16 + rh * 8 + r4;
                if (m < N) {
                    float* pd = g_AB + (size_t)m * 256 + half * 128;
                    #pragma unroll
                    for (int nt = 0; nt < 4; ++nt) {
                        int col = warpn * 32 + nt * 8 + q * 2;
                        float vx = acc[i][nt][rh * 2 + 0];
                        float vy = acc[i][nt][rh * 2 + 1];
                        if (half == 1) {
                            float2 bb = *reinterpret_cast<const float2*>(b_e + col);
                            vx += bb.x; vy += bb.y;
                        }
                        *reinterpret_cast<float2*>(pd + col) = make_float2(vx, vy);
                    }
                }
            }
        __syncthreads();
        t = tn;
    }
}

// k_edge: persistent; idx preloaded + deg red before MMA; batched epilogue
__global__ void __launch_bounds__(256, 3)
k_edge(const float* __restrict__ ef, const int* __restrict__ src,
       const int* __restrict__ dst, float* __restrict__ e_out, int E) {
    extern __shared__ char smem[];
    uint32_t sa = smem_u32(smem);
    int tid = threadIdx.x, lane = tid & 31, warp = tid >> 5;
    int warpm = warp >> 2, warpn = warp & 3;
    int ntiles = E >> 6;
    int q = lane & 3, r4 = lane >> 2;
    int row = tid >> 2, qq = tid & 3;

    int t = blockIdx.x;
    if (t >= ntiles) return;

    float4 P[4];
    {
        const float4* gr = reinterpret_cast<const float4*>(ef + (size_t)(t * 64 + row) * D + qq * 32);
        #pragma unroll
        for (int j = 0; j < 4; ++j) P[j] = __ldcs(gr + j);
    }

    while (t < ntiles) {
        {   // fill A: prefetched half + direct (streaming) half
            const float4* gr = reinterpret_cast<const float4*>(ef + (size_t)(t * 64 + row) * D + qq * 32);
            float4 Dq[4];
            #pragma unroll
            for (int j = 0; j < 4; ++j) Dq[j] = __ldcs(gr + 4 + j);
            char* ph = smem + row * ROWB + qq * 64;
            cvt_store(ph, P[0], P[1], 0, 1.f);
            cvt_store(ph, P[2], P[3], 1, 1.f);
            cvt_store(ph, Dq[0], Dq[1], 2, 1.f);
            cvt_store(ph, Dq[2], Dq[3], 3, 1.f);
        }
        __syncthreads();
        int tn = t + gridDim.x;
        if (tn < ntiles) {
            const float4* gr = reinterpret_cast<const float4*>(ef + (size_t)(tn * 64 + row) * D + qq * 32);
            #pragma unroll
            for (int j = 0; j < 4; ++j) P[j] = __ldcs(gr + j);
        }

        // preload indices + deg reduction (acc-independent; hides under MMA)
        int mbase = t * 64;
        int sidx[2][2], didx[2][2];
        #pragma unroll
        for (int i = 0; i < 2; ++i)
            #pragma unroll
            for (int rh = 0; rh < 2; ++rh) {
                int m = mbase + warpm * 32 + i * 16 + rh * 8 + r4;
                sidx[i][rh] = __ldg(src + m);
                didx[i][rh] = __ldg(dst + m);
                if (q == 0 && warpn == 0) atomicAdd(&g_deg[didx[i][rh]], 1.0f);
            }

        float acc[2][4][4];
        ZERO_ACC(acc);
        run_mma(sa, 2, warpm, warpn, lane, acc);

        #pragma unroll
        for (int i = 0; i < 2; ++i)
            #pragma unroll
            for (int rh = 0; rh < 2; ++rh) {
                int rl = warpm * 32 + i * 16 + rh * 8 + r4;
                int m = mbase + rl;
                const float* pA = g_AB + (size_t)sidx[i][rh] * 256;
                const float* pB = g_AB + (size_t)didx[i][rh] * 256 + 128;
                float* pe = e_out + (size_t)m * D;
                float* pg = g_agg + (size_t)didx[i][rh] * D;
                #pragma unroll
                for (int nt = 0; nt < 4; ++nt) {
                    int col = warpn * 32 + nt * 8 + q * 2;
                    float2 av = ldcg2(pA + col);
                    float2 bv = ldcg2(pB + col);
                    float vx = acc[i][nt][rh * 2 + 0] + av.x + bv.x;
                    float vy = acc[i][nt][rh * 2 + 1] + av.y + bv.y;
                    __stcs(reinterpret_cast<float2*>(pe + col), make_float2(vx, vy));
                    red_v2(pg + col, vx, vy);
                }
            }
        __syncthreads();
        t = tn;
    }
}

// k_node: persistent; two K-stages (nf, agg/deg)
__global__ void __launch_bounds__(256, 3)
k_node(const float* __restrict__ nf, const float* __restrict__ b_n,
       float* __restrict__ n_out, int N) {
    extern __shared__ char smem[];
    uint32_t sa = smem_u32(smem);
    int tid = threadIdx.x, lane = tid & 31, warp = tid >> 5;
    int warpm = warp >> 2, warpn = warp & 3;
    int ntiles = (N + 63) >> 6;
    int q = lane & 3, r4 = lane >> 2;
    int row = tid >> 2, qq = tid & 3;

    for (int t = blockIdx.x; t < ntiles; t += gridDim.x) {
        int mbase = t * 64;
        int nrows = min(64, N - mbase);

        {
            bool v = row < nrows;
            const float4* gr = reinterpret_cast<const float4*>(nf + (size_t)(mbase + row) * D + qq * 32);
            char* ph = smem + row * ROWB + qq * 64;
            #pragma unroll
            for (int jj = 0; jj < 4; ++jj) {
                float4 f0 = v ? __ldg(gr + 2 * jj)     : make_float4(0.f, 0.f, 0.f, 0.f);
                float4 f1 = v ? __ldg(gr + 2 * jj + 1) : make_float4(0.f, 0.f, 0.f, 0.f);
                cvt_store(ph, f0, f1, jj, 1.f);
            }
        }
        __syncthreads();

        float acc[2][4][4];
        ZERO_ACC(acc);
        run_mma(sa, 3, warpm, warpn, lane, acc);
        __syncthreads();

        {
            bool v = row < nrows;
            float s = v ? 1.f / fmaxf(__ldg(g_deg + mbase + row), 1.f) : 1.f;
            const float4* gr = reinterpret_cast<const float4*>(g_agg + (size_t)(mbase + row) * D + qq * 32);
            char* ph = smem + row * ROWB + qq * 64;
            #pragma unroll
            for (int jj = 0; jj < 4; ++jj) {
                float4 f0 = v ? __ldg(gr + 2 * jj)     : make_float4(0.f, 0.f, 0.f, 0.f);
                float4 f1 = v ? __ldg(gr + 2 * jj + 1) : make_float4(0.f, 0.f, 0.f, 0.f);
                cvt_store(ph, f0, f1, jj, s);
            }
        }
        __syncthreads();
        run_mma(sa, 4, warpm, warpn, lane, acc);

        #pragma unroll
        for (int i = 0; i < 2; ++i)
            #pragma unroll
            for (int rh = 0; rh < 2; ++rh) {
                int m = mbase + warpm * 32 + i * 16 + rh * 8 + r4;
                if (m < N) {
                    float* pd = n_out + (size_t)m * D;
                    #pragma unroll
                    for (int nt = 0; nt < 4; ++nt) {
                        int col = warpn * 32 + nt * 8 + q * 2;
                        float2 bb = *reinterpret_cast<const float2*>(b_n + col);
                        *reinterpret_cast<float2*>(pd + col) =
                            make_float2(acc[i][nt][rh * 2 + 0] + bb.x,
                                        acc[i][nt][rh * 2 + 1] + bb.y);
                    }
                }
            }
        __syncthreads();
    }
}

// ---------------------------------------------------------------------------
extern "C" void kernel_launch(void* const* d_in, const int* in_sizes, int n_in,
                              void* d_out, int out_size) {
    const float* nf  = (const float*)d_in[0];
    const float* ef  = (const float*)d_in[1];
    const int*   src = (const int*)d_in[2];   // int32 (JAX x64 disabled)
    const int*   dst = (const int*)d_in[3];
    const float* We  = (const float*)d_in[4];
    const float* be  = (const float*)d_in[5];
    const float* Wn  = (const float*)d_in[6];
    const float* bn  = (const float*)d_in[7];

    int N = in_sizes[0] / D;
    int E = in_sizes[1] / D;

    float* n_out = (float*)d_out;
    float* e_out = n_out + (size_t)N * D;

    cudaFuncSetAttribute(k_pre,  cudaFuncAttributeMaxDynamicSharedMemorySize, SMEM_TILE);
    cudaFuncSetAttribute(k_edge, cudaFuncAttributeMaxDynamicSharedMemorySize, SMEM_TILE);
    cudaFuncSetAttribute(k_node, cudaFuncAttributeMaxDynamicSharedMemorySize, SMEM_TILE);

    int zthreads = N * (D / 4);
    k_zero<<<(zthreads + 255) / 256, 256>>>(N);
    k_wprep<<<(5 * 2 * 2048 + 255) / 256, 256>>>(We, Wn);

    dim3 gpre(444, 2);
    k_pre<<<gpre, 256, SMEM_TILE>>>(nf, be, N);
    k_edge<<<444, 256, SMEM_TILE>>>(ef, src, dst, e_out, E);
    k_node<<<444, 256, SMEM_TILE>>>(nf, bn, n_out, N);
}